// round 1
// baseline (speedup 1.0000x reference)
#include <cuda_runtime.h>
#include <cstdint>
#include <cstdio>

#define B_  64
#define T_  256
#define C_  2048
#define HS_ 128
#define M_  (B_ * T_)   // 16384 rows

// Scratch for projections (no cudaMalloc allowed) — 3 x 8 MB
__device__ float g_k[M_ * HS_];
__device__ float g_q[M_ * HS_];
__device__ float g_v[M_ * HS_];

__device__ __forceinline__ unsigned f2tf32(float f) {
    unsigned r;
    asm("cvt.rna.tf32.f32 %0, %1;" : "=r"(r) : "f"(f));
    return r;
}

// ----------------------------------------------------------------------------
// Projection GEMM: out[M,128] = x[M,2048] @ W[2048,128], tf32 MMA, fp32 accum.
// Block tile 128x128, BK=32, 256 threads = 8 warps (4x2), warp tile 32x64.
// blockIdx.y selects which weight / output.
// ----------------------------------------------------------------------------
__global__ __launch_bounds__(256, 2) void proj_kernel(
    const float* __restrict__ x,
    const float* __restrict__ Wk,
    const float* __restrict__ Wq,
    const float* __restrict__ Wv)
{
    const float* W;
    float* out;
    if (blockIdx.y == 0)      { W = Wk; out = g_k; }
    else if (blockIdx.y == 1) { W = Wq; out = g_q; }
    else                      { W = Wv; out = g_v; }

    // stride 36 => A-frag LDS addresses are 4*(lane>>2) + (lane&3) mod 32: conflict-free
    __shared__ unsigned As[128][36];   // [m][k]
    __shared__ unsigned Bs[128][36];   // [n][k]  (W transposed)

    const int tid  = threadIdx.x;
    const int warp = tid >> 5, lane = tid & 31;
    const int wm = warp >> 1, wn = warp & 1;    // warp m-base wm*32, n-base wn*64
    const int m0 = blockIdx.x * 128;

    float acc[2][8][4] = {};

    for (int k0 = 0; k0 < C_; k0 += 32) {
        __syncthreads();   // previous iteration's reads done before overwrite
        // Load A tile: 128 rows x 32 cols = 1024 float4
        #pragma unroll
        for (int i = 0; i < 4; i++) {
            int idx = tid + i * 256;
            int r = idx >> 3, c4 = idx & 7;
            float4 v = *(const float4*)(x + (size_t)(m0 + r) * C_ + k0 + c4 * 4);
            As[r][c4 * 4 + 0] = f2tf32(v.x);
            As[r][c4 * 4 + 1] = f2tf32(v.y);
            As[r][c4 * 4 + 2] = f2tf32(v.z);
            As[r][c4 * 4 + 3] = f2tf32(v.w);
        }
        // Load B tile transposed: W rows k0..k0+31, all 128 n
        #pragma unroll
        for (int i = 0; i < 4; i++) {
            int idx = tid + i * 256;
            int kr = idx >> 5, n4 = idx & 31;
            float4 v = *(const float4*)(W + (size_t)(k0 + kr) * HS_ + n4 * 4);
            Bs[n4 * 4 + 0][kr] = f2tf32(v.x);
            Bs[n4 * 4 + 1][kr] = f2tf32(v.y);
            Bs[n4 * 4 + 2][kr] = f2tf32(v.z);
            Bs[n4 * 4 + 3][kr] = f2tf32(v.w);
        }
        __syncthreads();

        #pragma unroll
        for (int ks = 0; ks < 32; ks += 8) {
            unsigned a[2][4], b[8][2];
            #pragma unroll
            for (int mi = 0; mi < 2; mi++) {
                int row = wm * 32 + mi * 16 + (lane >> 2);
                int col = ks + (lane & 3);
                a[mi][0] = As[row][col];
                a[mi][1] = As[row + 8][col];
                a[mi][2] = As[row][col + 4];
                a[mi][3] = As[row + 8][col + 4];
            }
            #pragma unroll
            for (int ni = 0; ni < 8; ni++) {
                int n  = wn * 64 + ni * 8 + (lane >> 2);
                int kk = ks + (lane & 3);
                b[ni][0] = Bs[n][kk];
                b[ni][1] = Bs[n][kk + 4];
            }
            #pragma unroll
            for (int mi = 0; mi < 2; mi++)
                #pragma unroll
                for (int ni = 0; ni < 8; ni++)
                    asm volatile(
                        "mma.sync.aligned.m16n8k8.row.col.f32.tf32.tf32.f32 "
                        "{%0,%1,%2,%3}, {%4,%5,%6,%7}, {%8,%9}, {%0,%1,%2,%3};"
                        : "+f"(acc[mi][ni][0]), "+f"(acc[mi][ni][1]),
                          "+f"(acc[mi][ni][2]), "+f"(acc[mi][ni][3])
                        : "r"(a[mi][0]), "r"(a[mi][1]), "r"(a[mi][2]), "r"(a[mi][3]),
                          "r"(b[ni][0]), "r"(b[ni][1]));
        }
    }

    // Store accumulators (fp32)
    #pragma unroll
    for (int mi = 0; mi < 2; mi++) {
        int row0 = m0 + wm * 32 + mi * 16 + (lane >> 2);
        #pragma unroll
        for (int ni = 0; ni < 8; ni++) {
            int col = wn * 64 + ni * 8 + (lane & 3) * 2;
            out[(size_t)row0 * HS_ + col]           = acc[mi][ni][0];
            out[(size_t)row0 * HS_ + col + 1]       = acc[mi][ni][1];
            out[(size_t)(row0 + 8) * HS_ + col]     = acc[mi][ni][2];
            out[(size_t)(row0 + 8) * HS_ + col + 1] = acc[mi][ni][3];
        }
    }
}

// ----------------------------------------------------------------------------
// Attention: one block per (batch b, 64-row t-tile).
// scores[t,s] = dot(K[b,t], Q[b,s]) * C^-0.5, causal s<=t, softmax over s,
// out[t,h] = sum_s w[t,s] * V[b,s,h].
// smem: sc[64][256] fp32 + kt[64][132] + qv[64][132]  = 130 KB (dynamic).
// ----------------------------------------------------------------------------
__global__ __launch_bounds__(256) void attn_kernel(float* __restrict__ out)
{
    extern __shared__ float sm[];
    float* sc = sm;                    // [64][256]
    float* kt = sm + 64 * 256;         // [64][132]
    float* qv = kt + 64 * 132;         // [64][132]

    const int b  = blockIdx.y;
    const int bt = blockIdx.x;
    const int tid = threadIdx.x;
    const int t0 = bt * 64;
    const float scale = rsqrtf((float)C_);

    // init scores to -inf (covers s-tiles beyond the causal boundary)
    for (int i = tid; i < 64 * 256; i += 256) sc[i] = -INFINITY;

    // load K tile (rows t0..t0+63)
    for (int i = tid; i < 64 * 32; i += 256) {
        int r = i >> 5, c4 = i & 31;
        float4 v = *(const float4*)(g_k + ((size_t)(b * T_ + t0 + r)) * HS_ + c4 * 4);
        *(float4*)(kt + r * 132 + c4 * 4) = v;
    }
    __syncthreads();

    const int n_stiles = bt + 1;
    const int tx = tid & 15, ty = tid >> 4;   // 16x16 thread grid, 4x4 microtile

    // ---- phase 1: scores ----
    for (int st = 0; st < n_stiles; st++) {
        int s0 = st * 64;
        for (int i = tid; i < 64 * 32; i += 256) {
            int r = i >> 5, c4 = i & 31;
            float4 v = *(const float4*)(g_q + ((size_t)(b * T_ + s0 + r)) * HS_ + c4 * 4);
            *(float4*)(qv + r * 132 + c4 * 4) = v;
        }
        __syncthreads();

        float acc[4][4] = {};
        #pragma unroll 4
        for (int k4 = 0; k4 < 32; k4++) {
            float4 ka[4], qa[4];
            #pragma unroll
            for (int i = 0; i < 4; i++) ka[i] = *(float4*)(kt + (ty * 4 + i) * 132 + k4 * 4);
            #pragma unroll
            for (int j = 0; j < 4; j++) qa[j] = *(float4*)(qv + (tx * 4 + j) * 132 + k4 * 4);
            #pragma unroll
            for (int i = 0; i < 4; i++)
                #pragma unroll
                for (int j = 0; j < 4; j++)
                    acc[i][j] += ka[i].x * qa[j].x + ka[i].y * qa[j].y +
                                 ka[i].z * qa[j].z + ka[i].w * qa[j].w;
        }
        #pragma unroll
        for (int i = 0; i < 4; i++) {
            int t = t0 + ty * 4 + i;
            #pragma unroll
            for (int j = 0; j < 4; j++) {
                int s = s0 + tx * 4 + j;
                sc[(ty * 4 + i) * 256 + s] = (s <= t) ? acc[i][j] * scale : -INFINITY;
            }
        }
        __syncthreads();
    }

    // ---- phase 2: softmax (one warp handles 8 rows) ----
    const int warp = tid >> 5, lane = tid & 31;
    for (int r = 0; r < 8; r++) {
        float* p = sc + (warp * 8 + r) * 256;
        float m = -INFINITY;
        #pragma unroll
        for (int c = lane; c < 256; c += 32) m = fmaxf(m, p[c]);
        #pragma unroll
        for (int o = 16; o; o >>= 1) m = fmaxf(m, __shfl_xor_sync(0xffffffffu, m, o));
        float sum = 0.f;
        #pragma unroll
        for (int c = lane; c < 256; c += 32) { float e = __expf(p[c] - m); p[c] = e; sum += e; }
        #pragma unroll
        for (int o = 16; o; o >>= 1) sum += __shfl_xor_sync(0xffffffffu, sum, o);
        float inv = 1.f / sum;
        #pragma unroll
        for (int c = lane; c < 256; c += 32) p[c] *= inv;
    }
    __syncthreads();

    // ---- phase 3: out = W @ V. warp owns 8 t-rows, lane owns 4 h cols ----
    float oacc[8][4] = {};
    for (int st = 0; st < n_stiles; st++) {
        int s0 = st * 64;
        for (int i = tid; i < 64 * 32; i += 256) {
            int r = i >> 5, c4 = i & 31;
            float4 v = *(const float4*)(g_v + ((size_t)(b * T_ + s0 + r)) * HS_ + c4 * 4);
            *(float4*)(qv + r * 132 + c4 * 4) = v;
        }
        __syncthreads();

        #pragma unroll 4
        for (int sl = 0; sl < 64; sl++) {
            float4 vv = *(float4*)(qv + sl * 132 + lane * 4);
            #pragma unroll
            for (int i = 0; i < 8; i++) {
                float w = sc[(warp * 8 + i) * 256 + s0 + sl];   // broadcast within warp
                oacc[i][0] += w * vv.x;
                oacc[i][1] += w * vv.y;
                oacc[i][2] += w * vv.z;
                oacc[i][3] += w * vv.w;
            }
        }
        __syncthreads();
    }

    #pragma unroll
    for (int i = 0; i < 8; i++) {
        size_t off = ((size_t)b * T_ + t0 + warp * 8 + i) * HS_ + lane * 4;
        *(float4*)(out + off) = make_float4(oacc[i][0], oacc[i][1], oacc[i][2], oacc[i][3]);
    }
}

// ----------------------------------------------------------------------------
extern "C" void kernel_launch(void* const* d_in, const int* in_sizes, int n_in,
                              void* d_out, int out_size)
{
    (void)in_sizes; (void)n_in; (void)out_size;
    const float* x  = (const float*)d_in[0];
    const float* Wk = (const float*)d_in[1];
    const float* Wq = (const float*)d_in[2];
    const float* Wv = (const float*)d_in[3];

    dim3 gp(M_ / 128, 3);
    proj_kernel<<<gp, 256>>>(x, Wk, Wq, Wv);

    const int smem = (64 * 256 + 2 * 64 * 132) * (int)sizeof(float);  // 133120 B
    cudaFuncSetAttribute(attn_kernel, cudaFuncAttributeMaxDynamicSharedMemorySize, smem);
    dim3 ga(T_ / 64, B_);
    attn_kernel<<<ga, 256, smem>>>((float*)d_out);
}

// round 2
// speedup vs baseline: 1.8782x; 1.8782x over previous
#include <cuda_runtime.h>
#include <cstdint>

#define B_  64
#define T_  256
#define C_  2048
#define HS_ 128
#define M_  (B_ * T_)   // 16384 rows

// Scratch for projections (no cudaMalloc allowed) — 3 x 8 MB
__device__ float g_k[M_ * HS_];
__device__ float g_q[M_ * HS_];
__device__ float g_v[M_ * HS_];

__device__ __forceinline__ unsigned f2tf32(float f) {
    unsigned r;
    asm("cvt.rna.tf32.f32 %0, %1;" : "=r"(r) : "f"(f));
    return r;
}

__device__ __forceinline__ void cpa16(void* dst_smem, const void* src_gmem) {
    unsigned d = (unsigned)__cvta_generic_to_shared(dst_smem);
    asm volatile("cp.async.cg.shared.global [%0], [%1], 16;" :: "r"(d), "l"(src_gmem));
}
#define CP_COMMIT asm volatile("cp.async.commit_group;")
#define CP_WAIT(n) asm volatile("cp.async.wait_group %0;" :: "n"(n))

// ----------------------------------------------------------------------------
// Projection GEMM: out[M,128] = x[M,2048] @ W[2048,128]
// tf32 MMA (cvt at fragment load), 3-stage cp.async pipeline.
// Block 128x128xBK32, 256 thr = 8 warps (4x2), warp tile 32x64. 2 CTA/SM.
// smem per stage: A [128][36] fp32 + B [32][132] fp32 (k-major).
// ----------------------------------------------------------------------------
#define PS_A (128 * 36)
#define PS_B (32 * 132)
#define PS   (PS_A + PS_B)
#define NT   (C_ / 32)       // 64 k-tiles

__global__ __launch_bounds__(256, 2) void proj_kernel(
    const float* __restrict__ x,
    const float* __restrict__ Wk,
    const float* __restrict__ Wq,
    const float* __restrict__ Wv)
{
    extern __shared__ float psm[];

    const float* W;
    float* out;
    if (blockIdx.x == 0)      { W = Wk; out = g_k; }
    else if (blockIdx.x == 1) { W = Wq; out = g_q; }
    else                      { W = Wv; out = g_v; }

    const int tid  = threadIdx.x;
    const int warp = tid >> 5, lane = tid & 31;
    const int wm = warp >> 1, wn = warp & 1;
    const int m0 = blockIdx.y * 128;

    // precomputed per-thread load indices
    const int ar = tid >> 3, ac4 = tid & 7;     // A chunk base (stride 32 rows per i)
    const int bk = tid >> 5, bn4 = tid & 31;    // B chunk base (stride 8 k-rows per i)

    auto load_tile = [&](int stg, int kt) {
        float* As = psm + stg * PS;
        float* Bs = As + PS_A;
        const int k0 = kt * 32;
        #pragma unroll
        for (int i = 0; i < 4; i++) {
            int r = ar + i * 32;
            cpa16(As + r * 36 + ac4 * 4,
                  x + (size_t)(m0 + r) * C_ + k0 + ac4 * 4);
        }
        #pragma unroll
        for (int i = 0; i < 4; i++) {
            int kr = bk + i * 8;
            cpa16(Bs + kr * 132 + bn4 * 4,
                  W + (size_t)(k0 + kr) * HS_ + bn4 * 4);
        }
        CP_COMMIT;
    };

    load_tile(0, 0);
    load_tile(1, 1);

    float acc[2][8][4] = {};

    for (int it = 0; it < NT; it++) {
        if (it < NT - 1) { CP_WAIT(1); } else { CP_WAIT(0); }
        __syncthreads();

        const float* As = psm + (it % 3) * PS;
        const float* Bs = As + PS_A;

        #pragma unroll
        for (int ks = 0; ks < 32; ks += 8) {
            unsigned a[2][4], b[8][2];
            #pragma unroll
            for (int mi = 0; mi < 2; mi++) {
                int row = wm * 32 + mi * 16 + (lane >> 2);
                int col = ks + (lane & 3);
                a[mi][0] = f2tf32(As[row * 36 + col]);
                a[mi][1] = f2tf32(As[(row + 8) * 36 + col]);
                a[mi][2] = f2tf32(As[row * 36 + col + 4]);
                a[mi][3] = f2tf32(As[(row + 8) * 36 + col + 4]);
            }
            #pragma unroll
            for (int ni = 0; ni < 8; ni++) {
                int n  = wn * 64 + ni * 8 + (lane >> 2);
                int kk = ks + (lane & 3);
                b[ni][0] = f2tf32(Bs[kk * 132 + n]);
                b[ni][1] = f2tf32(Bs[(kk + 4) * 132 + n]);
            }
            #pragma unroll
            for (int mi = 0; mi < 2; mi++)
                #pragma unroll
                for (int ni = 0; ni < 8; ni++)
                    asm volatile(
                        "mma.sync.aligned.m16n8k8.row.col.f32.tf32.tf32.f32 "
                        "{%0,%1,%2,%3}, {%4,%5,%6,%7}, {%8,%9}, {%0,%1,%2,%3};"
                        : "+f"(acc[mi][ni][0]), "+f"(acc[mi][ni][1]),
                          "+f"(acc[mi][ni][2]), "+f"(acc[mi][ni][3])
                        : "r"(a[mi][0]), "r"(a[mi][1]), "r"(a[mi][2]), "r"(a[mi][3]),
                          "r"(b[ni][0]), "r"(b[ni][1]));
        }

        if (it + 2 < NT) load_tile((it + 2) % 3, it + 2);
    }

    #pragma unroll
    for (int mi = 0; mi < 2; mi++) {
        int row0 = m0 + wm * 32 + mi * 16 + (lane >> 2);
        #pragma unroll
        for (int ni = 0; ni < 8; ni++) {
            int col = wn * 64 + ni * 8 + (lane & 3) * 2;
            out[(size_t)row0 * HS_ + col]           = acc[mi][ni][0];
            out[(size_t)row0 * HS_ + col + 1]       = acc[mi][ni][1];
            out[(size_t)(row0 + 8) * HS_ + col]     = acc[mi][ni][2];
            out[(size_t)(row0 + 8) * HS_ + col + 1] = acc[mi][ni][3];
        }
    }
}

// ----------------------------------------------------------------------------
// Attention, flash-style: block = (bt, b), 64 t-rows, online softmax over
// s-tiles of 64. smem: sc[64][68] + kt[64][132] + qv[64][132] = 83 KB → 2 CTA/SM.
// ----------------------------------------------------------------------------
__global__ __launch_bounds__(256, 2) void attn_kernel(float* __restrict__ out)
{
    extern __shared__ float sm[];
    float* sc = sm;                  // [64][68]
    float* kt = sm + 64 * 68;        // [64][132]
    float* qv = kt + 64 * 132;       // [64][132]

    const int b  = blockIdx.y;
    const int bt = blockIdx.x;
    const int tid = threadIdx.x;
    const int warp = tid >> 5, lane = tid & 31;
    const int tx = tid & 15, ty = tid >> 4;
    const int t0 = bt * 64;
    const float scale = rsqrtf((float)C_);

    // K tile (rows t0..t0+63)
    for (int i = tid; i < 64 * 32; i += 256) {
        int r = i >> 5, c4 = i & 31;
        float4 v = *(const float4*)(g_k + ((size_t)(b * T_ + t0 + r)) * HS_ + c4 * 4);
        *(float4*)(kt + r * 132 + c4 * 4) = v;
    }

    float m_r[8], l_r[8], oacc[8][4];
    #pragma unroll
    for (int i = 0; i < 8; i++) {
        m_r[i] = -INFINITY; l_r[i] = 0.f;
        oacc[i][0] = oacc[i][1] = oacc[i][2] = oacc[i][3] = 0.f;
    }

    const int n_stiles = bt + 1;
    for (int st = 0; st < n_stiles; st++) {
        const int s0 = st * 64;

        // Q tile -> qv
        for (int i = tid; i < 64 * 32; i += 256) {
            int r = i >> 5, c4 = i & 31;
            float4 v = *(const float4*)(g_q + ((size_t)(b * T_ + s0 + r)) * HS_ + c4 * 4);
            *(float4*)(qv + r * 132 + c4 * 4) = v;
        }
        __syncthreads();   // (A) kt (first iter) + qv ready

        // scores: thread (ty,tx) -> rows ty*4+i, cols tx+16j (interleaved)
        float acc[4][4] = {};
        #pragma unroll 4
        for (int k4 = 0; k4 < 32; k4++) {
            float4 ka[4], qa[4];
            #pragma unroll
            for (int i = 0; i < 4; i++) ka[i] = *(float4*)(kt + (ty * 4 + i) * 132 + k4 * 4);
            #pragma unroll
            for (int j = 0; j < 4; j++) qa[j] = *(float4*)(qv + (tx + 16 * j) * 132 + k4 * 4);
            #pragma unroll
            for (int i = 0; i < 4; i++)
                #pragma unroll
                for (int j = 0; j < 4; j++)
                    acc[i][j] += ka[i].x * qa[j].x + ka[i].y * qa[j].y +
                                 ka[i].z * qa[j].z + ka[i].w * qa[j].w;
        }
        const bool diag = (st == bt);
        #pragma unroll
        for (int i = 0; i < 4; i++) {
            int t = t0 + ty * 4 + i;
            #pragma unroll
            for (int j = 0; j < 4; j++) {
                int s = s0 + tx + 16 * j;
                sc[(ty * 4 + i) * 68 + tx + 16 * j] =
                    (!diag || s <= t) ? acc[i][j] * scale : -INFINITY;
            }
        }
        __syncthreads();   // (B) scores visible; all qv reads done

        // V tile -> qv (overlaps with softmax below)
        for (int i = tid; i < 64 * 32; i += 256) {
            int r = i >> 5, c4 = i & 31;
            float4 v = *(const float4*)(g_v + ((size_t)(b * T_ + s0 + r)) * HS_ + c4 * 4);
            *(float4*)(qv + r * 132 + c4 * 4) = v;
        }

        // online softmax: warp owns rows warp*8..+7 (written by this warp's threads)
        #pragma unroll
        for (int i = 0; i < 8; i++) {
            float* p = sc + (warp * 8 + i) * 68;
            float s1 = p[lane], s2 = p[lane + 32];
            float mt = fmaxf(s1, s2);
            #pragma unroll
            for (int o = 16; o; o >>= 1) mt = fmaxf(mt, __shfl_xor_sync(0xffffffffu, mt, o));
            float mn = fmaxf(m_r[i], mt);
            float f = __expf(m_r[i] - mn);
            float e1 = __expf(s1 - mn), e2 = __expf(s2 - mn);
            p[lane] = e1; p[lane + 32] = e2;
            float sum = e1 + e2;
            #pragma unroll
            for (int o = 16; o; o >>= 1) sum += __shfl_xor_sync(0xffffffffu, sum, o);
            l_r[i] = l_r[i] * f + sum;
            m_r[i] = mn;
            oacc[i][0] *= f; oacc[i][1] *= f; oacc[i][2] *= f; oacc[i][3] *= f;
        }
        __syncthreads();   // (C) V ready

        // PV: warp rows warp*8..+7, lane cols lane*4..+3
        #pragma unroll 4
        for (int sl = 0; sl < 64; sl++) {
            float4 vv = *(float4*)(qv + sl * 132 + lane * 4);
            #pragma unroll
            for (int i = 0; i < 8; i++) {
                float w = sc[(warp * 8 + i) * 68 + sl];
                oacc[i][0] += w * vv.x;
                oacc[i][1] += w * vv.y;
                oacc[i][2] += w * vv.z;
                oacc[i][3] += w * vv.w;
            }
        }
        __syncthreads();   // (D) qv/sc free for next iteration
    }

    #pragma unroll
    for (int i = 0; i < 8; i++) {
        float inv = 1.f / l_r[i];
        size_t off = ((size_t)b * T_ + t0 + warp * 8 + i) * HS_ + lane * 4;
        *(float4*)(out + off) = make_float4(oacc[i][0] * inv, oacc[i][1] * inv,
                                            oacc[i][2] * inv, oacc[i][3] * inv);
    }
}

// ----------------------------------------------------------------------------
extern "C" void kernel_launch(void* const* d_in, const int* in_sizes, int n_in,
                              void* d_out, int out_size)
{
    (void)in_sizes; (void)n_in; (void)out_size;
    const float* x  = (const float*)d_in[0];
    const float* Wk = (const float*)d_in[1];
    const float* Wq = (const float*)d_in[2];
    const float* Wv = (const float*)d_in[3];

    const int psmem = 3 * PS * (int)sizeof(float);   // 105984 B
    cudaFuncSetAttribute(proj_kernel, cudaFuncAttributeMaxDynamicSharedMemorySize, psmem);
    proj_kernel<<<dim3(3, 128), 256, psmem>>>(x, Wk, Wq, Wv);

    const int asmem = (64 * 68 + 2 * 64 * 132) * (int)sizeof(float);  // 84992 B
    cudaFuncSetAttribute(attn_kernel, cudaFuncAttributeMaxDynamicSharedMemorySize, asmem);
    attn_kernel<<<dim3(4, 64), 256, asmem>>>((float*)d_out);
}

// round 4
// speedup vs baseline: 2.4705x; 1.3154x over previous
#include <cuda_runtime.h>
#include <cstdint>

#define B_  64
#define T_  256
#define C_  2048
#define HS_ 128
#define M_  (B_ * T_)

// Scratch (no cudaMalloc allowed)
__device__ float g_k[M_ * HS_];
__device__ float g_q[M_ * HS_];
__device__ float g_v[M_ * HS_];
__device__ float g_wt[3 * HS_ * C_];   // Wt[p][n][k], rna-rounded tf32, K-major

__device__ __forceinline__ unsigned f2tf32(float f) {
    unsigned r;
    asm("cvt.rna.tf32.f32 %0, %1;" : "=r"(r) : "f"(f));
    return r;
}
__device__ __forceinline__ void cpa16(void* dst_smem, const void* src_gmem) {
    unsigned d = (unsigned)__cvta_generic_to_shared(dst_smem);
    asm volatile("cp.async.cg.shared.global [%0], [%1], 16;" :: "r"(d), "l"(src_gmem));
}
#define CP_COMMIT asm volatile("cp.async.commit_group;")
#define CP_WAIT(n) asm volatile("cp.async.wait_group %0;" :: "n"(n))

#define MMA_TF32(acc, a, b)                                                     \
    asm volatile(                                                               \
        "mma.sync.aligned.m16n8k8.row.col.f32.tf32.tf32.f32 "                   \
        "{%0,%1,%2,%3}, {%4,%5,%6,%7}, {%8,%9}, {%0,%1,%2,%3};"                 \
        : "+f"((acc)[0]), "+f"((acc)[1]), "+f"((acc)[2]), "+f"((acc)[3])        \
        : "r"((a)[0]), "r"((a)[1]), "r"((a)[2]), "r"((a)[3]),                   \
          "r"((b)[0]), "r"((b)[1]))

// ----------------------------------------------------------------------------
// Prep: Wt[p][n][k] = rna_tf32(W_p[k][n])  (transpose + round, 3 MB)
// ----------------------------------------------------------------------------
__global__ void prep_wt(const float* __restrict__ Wk, const float* __restrict__ Wq,
                        const float* __restrict__ Wv)
{
    __shared__ float t[32][33];
    const float* W = blockIdx.z == 0 ? Wk : (blockIdx.z == 1 ? Wq : Wv);
    const int k0 = blockIdx.x * 32, n0 = blockIdx.y * 32;
    const int tx = threadIdx.x & 31, ty = threadIdx.x >> 5;   // 32 x 8
    #pragma unroll
    for (int i = 0; i < 32; i += 8)
        t[ty + i][tx] = W[(size_t)(k0 + ty + i) * HS_ + n0 + tx];
    __syncthreads();
    #pragma unroll
    for (int i = 0; i < 32; i += 8) {
        unsigned u = f2tf32(t[tx][ty + i]);
        g_wt[((size_t)blockIdx.z * HS_ + n0 + ty + i) * C_ + k0 + tx] = __uint_as_float(u);
    }
}

// ----------------------------------------------------------------------------
// Projection GEMM: out[M,128] = x[M,2048] @ W.  tf32 mma.sync, no in-loop cvt:
// A = raw fp32 x (HMMA truncates), B = pre-rounded g_wt.
// Block 128x128xBK32, 256 thr, warp tile 32x64, 3-stage cp.async. 2 CTA/SM.
// ----------------------------------------------------------------------------
#define PS_A (128 * 36)
#define PS_B (128 * 36)
#define PS   (PS_A + PS_B)
#define NKT  (C_ / 32)       // 64

__global__ __launch_bounds__(256, 2) void proj_kernel(const float* __restrict__ x)
{
    extern __shared__ float psm[];

    const int p = blockIdx.x;                 // projection index (fastest -> L2 reuse of x)
    float* out = p == 0 ? g_k : (p == 1 ? g_q : g_v);
    const float* Wp = g_wt + (size_t)p * HS_ * C_;

    const int tid  = threadIdx.x;
    const int warp = tid >> 5, lane = tid & 31;
    const int wm = warp >> 1, wn = warp & 1;
    const int m0 = blockIdx.y * 128;

    const int ar = tid >> 3, ac4 = tid & 7;

    auto load_tile = [&](int stg, int kt) {
        float* As = psm + stg * PS;
        float* Bs = As + PS_A;
        const int k0 = kt * 32;
        #pragma unroll
        for (int i = 0; i < 4; i++) {
            int r = ar + i * 32;
            cpa16(As + r * 36 + ac4 * 4, x + (size_t)(m0 + r) * C_ + k0 + ac4 * 4);
            cpa16(Bs + r * 36 + ac4 * 4, Wp + (size_t)r * C_ + k0 + ac4 * 4);
        }
        CP_COMMIT;
    };

    load_tile(0, 0);
    load_tile(1, 1);

    float acc[2][8][4] = {};

    for (int it = 0; it < NKT; it++) {
        if (it < NKT - 1) { CP_WAIT(1); } else { CP_WAIT(0); }
        __syncthreads();

        const float* As = psm + (it % 3) * PS;
        const float* Bs = As + PS_A;

        #pragma unroll
        for (int ks = 0; ks < 32; ks += 8) {
            unsigned a[2][4], b[8][2];
            #pragma unroll
            for (int mi = 0; mi < 2; mi++) {
                int row = wm * 32 + mi * 16 + (lane >> 2);
                int col = ks + (lane & 3);
                a[mi][0] = __float_as_uint(As[row * 36 + col]);
                a[mi][1] = __float_as_uint(As[(row + 8) * 36 + col]);
                a[mi][2] = __float_as_uint(As[row * 36 + col + 4]);
                a[mi][3] = __float_as_uint(As[(row + 8) * 36 + col + 4]);
            }
            #pragma unroll
            for (int ni = 0; ni < 8; ni++) {
                int n  = wn * 64 + ni * 8 + (lane >> 2);
                int kk = ks + (lane & 3);
                b[ni][0] = __float_as_uint(Bs[n * 36 + kk]);
                b[ni][1] = __float_as_uint(Bs[n * 36 + kk + 4]);
            }
            #pragma unroll
            for (int mi = 0; mi < 2; mi++)
                #pragma unroll
                for (int ni = 0; ni < 8; ni++)
                    MMA_TF32(acc[mi][ni], a[mi], b[ni]);
        }

        if (it + 2 < NKT) load_tile((it + 2) % 3, it + 2);
    }

    // store, rna-rounded to tf32 (attn consumes via tensor cores)
    #pragma unroll
    for (int mi = 0; mi < 2; mi++) {
        int row0 = m0 + wm * 32 + mi * 16 + (lane >> 2);
        #pragma unroll
        for (int ni = 0; ni < 8; ni++) {
            int col = wn * 64 + ni * 8 + (lane & 3) * 2;
            out[(size_t)row0 * HS_ + col]           = __uint_as_float(f2tf32(acc[mi][ni][0]));
            out[(size_t)row0 * HS_ + col + 1]       = __uint_as_float(f2tf32(acc[mi][ni][1]));
            out[(size_t)(row0 + 8) * HS_ + col]     = __uint_as_float(f2tf32(acc[mi][ni][2]));
            out[(size_t)(row0 + 8) * HS_ + col + 1] = __uint_as_float(f2tf32(acc[mi][ni][3]));
        }
    }
}

// ----------------------------------------------------------------------------
// Attention: flash-style, tensor-core S and PV, smem-mediated P.
// Block (bt, b): 64 t-rows. 8 warps: warp w -> rows band=(w&3)*16, half=(w>>2).
// ----------------------------------------------------------------------------
__global__ __launch_bounds__(256, 2) void attn_kernel(float* __restrict__ out)
{
    extern __shared__ float sm[];
    float* sc    = sm;                  // [64][68]  scores / P
    float* kt    = sm + 64 * 68;        // [64][132] K tile
    float* qv    = kt + 64 * 132;       // [64][132] Q then V tile
    float* f_row = qv + 64 * 132;       // [64]
    float* l_row = f_row + 64;          // [64]

    const int b  = blockIdx.y;
    const int bt = blockIdx.x;
    const int tid = threadIdx.x;
    const int warp = tid >> 5, lane = tid & 31;
    const int band = (warp & 3) * 16;   // mma row band
    const int half = warp >> 2;         // 0/1
    const int lr = lane >> 2, lc = lane & 3;
    const int t0 = bt * 64;
    const float scale = rsqrtf((float)C_);

    // K tile
    for (int i = tid; i < 64 * 32; i += 256) {
        int r = i >> 5, c4 = i & 31;
        float4 v = *(const float4*)(g_k + ((size_t)(b * T_ + t0 + r)) * HS_ + c4 * 4);
        *(float4*)(kt + r * 132 + c4 * 4) = v;
    }

    float m_r[8], l_r[8];
    float oacc[8][4] = {};   // PV acc: nt -> h cols half*64+nt*8+2lc(+1); rows band+lr(+8)
    #pragma unroll
    for (int i = 0; i < 8; i++) { m_r[i] = -INFINITY; l_r[i] = 0.f; }

    const int n_stiles = bt + 1;
    for (int st = 0; st < n_stiles; st++) {
        const int s0 = st * 64;

        // Q tile
        for (int i = tid; i < 64 * 32; i += 256) {
            int r = i >> 5, c4 = i & 31;
            float4 v = *(const float4*)(g_q + ((size_t)(b * T_ + s0 + r)) * HS_ + c4 * 4);
            *(float4*)(qv + r * 132 + c4 * 4) = v;
        }
        __syncthreads();   // (A) kt + qv(Q) ready

        // ---- S = K Q^T : warp covers rows band..band+15, cols half*32..+31 ----
        float sacc[4][4] = {};
        #pragma unroll
        for (int kk = 0; kk < 16; kk++) {
            unsigned a[4];
            const int arow = band + lr, acol = kk * 8 + lc;
            a[0] = __float_as_uint(kt[arow * 132 + acol]);
            a[1] = __float_as_uint(kt[(arow + 8) * 132 + acol]);
            a[2] = __float_as_uint(kt[arow * 132 + acol + 4]);
            a[3] = __float_as_uint(kt[(arow + 8) * 132 + acol + 4]);
            #pragma unroll
            for (int nt = 0; nt < 4; nt++) {
                unsigned bb[2];
                const int srow = half * 32 + nt * 8 + lr;
                bb[0] = __float_as_uint(qv[srow * 132 + acol]);
                bb[1] = __float_as_uint(qv[srow * 132 + acol + 4]);
                MMA_TF32(sacc[nt], a, bb);
            }
        }
        const bool diag = (st == bt);
        #pragma unroll
        for (int nt = 0; nt < 4; nt++) {
            const int row = band + lr, col = half * 32 + nt * 8 + 2 * lc;
            const int tg = t0 + row, sg = s0 + col;
            sc[row * 68 + col]       = (!diag || sg     <= tg)     ? sacc[nt][0] * scale : -INFINITY;
            sc[row * 68 + col + 1]   = (!diag || sg + 1 <= tg)     ? sacc[nt][1] * scale : -INFINITY;
            sc[(row + 8) * 68 + col]     = (!diag || sg     <= tg + 8) ? sacc[nt][2] * scale : -INFINITY;
            sc[(row + 8) * 68 + col + 1] = (!diag || sg + 1 <= tg + 8) ? sacc[nt][3] * scale : -INFINITY;
        }
        __syncthreads();   // (B) sc full; qv(Q) reads done

        // V tile (overwrites qv; overlaps softmax)
        for (int i = tid; i < 64 * 32; i += 256) {
            int r = i >> 5, c4 = i & 31;
            float4 v = *(const float4*)(g_v + ((size_t)(b * T_ + s0 + r)) * HS_ + c4 * 4);
            *(float4*)(qv + r * 132 + c4 * 4) = v;
        }

        // ---- online softmax: warp owns rows warp*8..+7 ----
        #pragma unroll
        for (int i = 0; i < 8; i++) {
            float* prow = sc + (warp * 8 + i) * 68;
            float s1 = prow[lane], s2 = prow[lane + 32];
            float mt = fmaxf(s1, s2);
            #pragma unroll
            for (int o = 16; o; o >>= 1) mt = fmaxf(mt, __shfl_xor_sync(0xffffffffu, mt, o));
            float mn = fmaxf(m_r[i], mt);
            float f = __expf(m_r[i] - mn);
            float e1 = __uint_as_float(f2tf32(__expf(s1 - mn)));
            float e2 = __uint_as_float(f2tf32(__expf(s2 - mn)));
            prow[lane] = e1; prow[lane + 32] = e2;
            float sum = e1 + e2;
            #pragma unroll
            for (int o = 16; o; o >>= 1) sum += __shfl_xor_sync(0xffffffffu, sum, o);
            l_r[i] = l_r[i] * f + sum;
            m_r[i] = mn;
            if (lane == 0) f_row[warp * 8 + i] = f;
        }
        __syncthreads();   // (C) P + V + f_row ready

        // rescale output accumulators
        {
            const float f1 = f_row[band + lr], f2 = f_row[band + lr + 8];
            #pragma unroll
            for (int nt = 0; nt < 8; nt++) {
                oacc[nt][0] *= f1; oacc[nt][1] *= f1;
                oacc[nt][2] *= f2; oacc[nt][3] *= f2;
            }
        }

        // ---- O += P V : warp rows band..+15, cols half*64..+63 ----
        #pragma unroll
        for (int kk = 0; kk < 8; kk++) {
            unsigned a[4];
            const int arow = band + lr, acol = kk * 8 + lc;
            a[0] = __float_as_uint(sc[arow * 68 + acol]);
            a[1] = __float_as_uint(sc[(arow + 8) * 68 + acol]);
            a[2] = __float_as_uint(sc[arow * 68 + acol + 4]);
            a[3] = __float_as_uint(sc[(arow + 8) * 68 + acol + 4]);
            #pragma unroll
            for (int nt = 0; nt < 8; nt++) {
                unsigned bb[2];
                const int hcol = half * 64 + nt * 8 + lr;
                bb[0] = __float_as_uint(qv[(kk * 8 + lc) * 132 + hcol]);
                bb[1] = __float_as_uint(qv[(kk * 8 + lc + 4) * 132 + hcol]);
                MMA_TF32(oacc[nt], a, bb);
            }
        }
        __syncthreads();   // (D) sc/qv free
    }

    if (lane == 0) {
        #pragma unroll
        for (int i = 0; i < 8; i++) l_row[warp * 8 + i] = l_r[i];
    }
    __syncthreads();

    {
        const float inv1 = 1.f / l_row[band + lr];
        const float inv2 = 1.f / l_row[band + lr + 8];
        const size_t r1 = (size_t)(b * T_ + t0 + band + lr) * HS_;
        const size_t r2 = (size_t)(b * T_ + t0 + band + lr + 8) * HS_;
        #pragma unroll
        for (int nt = 0; nt < 8; nt++) {
            const int col = half * 64 + nt * 8 + 2 * lc;
            *(float2*)(out + r1 + col) = make_float2(oacc[nt][0] * inv1, oacc[nt][1] * inv1);
            *(float2*)(out + r2 + col) = make_float2(oacc[nt][2] * inv2, oacc[nt][3] * inv2);
        }
    }
}

// ----------------------------------------------------------------------------
extern "C" void kernel_launch(void* const* d_in, const int* in_sizes, int n_in,
                              void* d_out, int out_size)
{
    (void)in_sizes; (void)n_in; (void)out_size;
    const float* x  = (const float*)d_in[0];
    const float* Wk = (const float*)d_in[1];
    const float* Wq = (const float*)d_in[2];
    const float* Wv = (const float*)d_in[3];

    prep_wt<<<dim3(C_ / 32, HS_ / 32, 3), 256>>>(Wk, Wq, Wv);

    const int psmem = 3 * PS * (int)sizeof(float);   // 110592 B
    cudaFuncSetAttribute(proj_kernel, cudaFuncAttributeMaxDynamicSharedMemorySize, psmem);
    proj_kernel<<<dim3(3, 128), 256, psmem>>>(x);

    const int asmem = (64 * 68 + 2 * 64 * 132 + 128) * (int)sizeof(float);  // 85504 B
    cudaFuncSetAttribute(attn_kernel, cudaFuncAttributeMaxDynamicSharedMemorySize, asmem);
    attn_kernel<<<dim3(4, 64), 256, asmem>>>((float*)d_out);
}

// round 5
// speedup vs baseline: 2.9017x; 1.1745x over previous
#include <cuda_runtime.h>
#include <cuda_fp16.h>
#include <cstdint>

#define B_  64
#define T_  256
#define C_  2048
#define HS_ 128
#define M_  (B_ * T_)

// Scratch (no cudaMalloc allowed)
__device__ float  g_k[M_ * HS_];
__device__ float  g_q[M_ * HS_];
__device__ float  g_v[M_ * HS_];
__device__ __half g_wh[3 * HS_ * C_];   // Wt[p][n][k], fp16 RNE, K-major

__device__ __forceinline__ unsigned f2tf32(float f) {
    unsigned r;
    asm("cvt.rna.tf32.f32 %0, %1;" : "=r"(r) : "f"(f));
    return r;
}
__device__ __forceinline__ void cpa16(void* dst_smem, const void* src_gmem) {
    unsigned d = (unsigned)__cvta_generic_to_shared(dst_smem);
    asm volatile("cp.async.cg.shared.global [%0], [%1], 16;" :: "r"(d), "l"(src_gmem));
}
#define CP_COMMIT  asm volatile("cp.async.commit_group;")
#define CP_WAIT(n) asm volatile("cp.async.wait_group %0;" :: "n"(n))

#define MMA_TF32(acc, a, b)                                                     \
    asm volatile(                                                               \
        "mma.sync.aligned.m16n8k8.row.col.f32.tf32.tf32.f32 "                   \
        "{%0,%1,%2,%3}, {%4,%5,%6,%7}, {%8,%9}, {%0,%1,%2,%3};"                 \
        : "+f"((acc)[0]), "+f"((acc)[1]), "+f"((acc)[2]), "+f"((acc)[3])        \
        : "r"((a)[0]), "r"((a)[1]), "r"((a)[2]), "r"((a)[3]),                   \
          "r"((b)[0]), "r"((b)[1]))

#define MMA_F16(acc, a, b)                                                      \
    asm volatile(                                                               \
        "mma.sync.aligned.m16n8k16.row.col.f32.f16.f16.f32 "                    \
        "{%0,%1,%2,%3}, {%4,%5,%6,%7}, {%8,%9}, {%0,%1,%2,%3};"                 \
        : "+f"((acc)[0]), "+f"((acc)[1]), "+f"((acc)[2]), "+f"((acc)[3])        \
        : "r"((a)[0]), "r"((a)[1]), "r"((a)[2]), "r"((a)[3]),                   \
          "r"((b)[0]), "r"((b)[1]))

// ----------------------------------------------------------------------------
// Prep: Wh[p][n][k] = fp16_rn(W_p[k][n])  (transpose + round, 1.5 MB out)
// ----------------------------------------------------------------------------
__global__ void prep_wt(const float* __restrict__ Wk, const float* __restrict__ Wq,
                        const float* __restrict__ Wv)
{
    __shared__ float t[32][33];
    const float* W = blockIdx.z == 0 ? Wk : (blockIdx.z == 1 ? Wq : Wv);
    const int k0 = blockIdx.x * 32, n0 = blockIdx.y * 32;
    const int tx = threadIdx.x & 31, ty = threadIdx.x >> 5;   // 32 x 8
    #pragma unroll
    for (int i = 0; i < 32; i += 8)
        t[ty + i][tx] = W[(size_t)(k0 + ty + i) * HS_ + n0 + tx];
    __syncthreads();
    #pragma unroll
    for (int i = 0; i < 32; i += 8)
        g_wh[((size_t)blockIdx.z * HS_ + n0 + ty + i) * C_ + k0 + tx] =
            __float2half_rn(t[tx][ty + i]);
}

// ----------------------------------------------------------------------------
// Projection GEMM (fp16 mma.sync m16n8k16): out[M,128] = x @ W_p.
// 512 threads, block tile 128x128xBK32. Warp grid 4x4, warp tile 32x32.
// B: 4-stage cp.async (fp16). A: LDG fp32 -> cvt f16x2 -> STS, double-buffered,
// pipelined one iteration ahead of the MMA.
// ----------------------------------------------------------------------------
#define NKT   (C_ / 32)            // 64 k-tiles
#define RS    40                    // smem row stride in fp16 units (80 B)
#define ABUF  (128 * RS)            // fp16 units per A buffer
#define BBUF  (128 * RS)            // fp16 units per B stage

__global__ __launch_bounds__(512, 1) void proj_kernel(const float* __restrict__ x)
{
    extern __shared__ __half hsm[];
    __half* Abuf = hsm;                 // 2 buffers
    __half* Bbuf = hsm + 2 * ABUF;      // 4 stages

    const int p = blockIdx.x;
    float* out = p == 0 ? g_k : (p == 1 ? g_q : g_v);
    const __half* Wp = g_wh + (size_t)p * HS_ * C_;

    const int tid  = threadIdx.x;
    const int warp = tid >> 5, lane = tid & 31;
    const int wm = warp >> 2, wn = warp & 3;        // 4x4 warps, 32x32 tiles
    const int lr = lane >> 2, lc = lane & 3;
    const int m0 = blockIdx.y * 128;

    // A conversion mapping: thread -> row = tid>>2, 8-float chunk = tid&3
    const int arow = tid >> 2, ach = tid & 3;
    // B cp.async mapping: thread -> n-row = tid>>2, 16B chunk = tid&3
    const int brow = tid >> 2, bch = tid & 3;

    auto ldgA = [&](int j, float4& v0, float4& v1) {
        const float* src = x + (size_t)(m0 + arow) * C_ + j * 32 + ach * 8;
        v0 = *(const float4*)src;
        v1 = *(const float4*)(src + 4);
    };
    auto stsA = [&](int buf, const float4& v0, const float4& v1) {
        __half2 h[4];
        h[0] = __floats2half2_rn(v0.x, v0.y);
        h[1] = __floats2half2_rn(v0.z, v0.w);
        h[2] = __floats2half2_rn(v1.x, v1.y);
        h[3] = __floats2half2_rn(v1.z, v1.w);
        *(uint4*)(Abuf + buf * ABUF + arow * RS + ach * 8) =
            *(reinterpret_cast<uint4*>(h));
    };
    auto cpaB = [&](int j) {
        cpa16(Bbuf + (j & 3) * BBUF + brow * RS + bch * 8,
              Wp + (size_t)brow * C_ + j * 32 + bch * 8);
    };

    // prologue
    cpaB(0); CP_COMMIT;
    cpaB(1); CP_COMMIT;
    cpaB(2); CP_COMMIT;
    float4 v0, v1;
    ldgA(0, v0, v1);
    stsA(0, v0, v1);
    ldgA(1, v0, v1);

    float acc[2][4][4] = {};

    for (int j = 0; j < NKT; j++) {
        CP_WAIT(2);
        __syncthreads();   // A(j) STS drained, B(j) visible, prev frag reads done

        const __half* As = Abuf + (j & 1) * ABUF;
        const __half* Bs = Bbuf + (j & 3) * BBUF;

        #pragma unroll
        for (int ks = 0; ks < 2; ks++) {
            unsigned a[2][4], b[4][2];
            #pragma unroll
            for (int mi = 0; mi < 2; mi++) {
                const int row = wm * 32 + mi * 16 + lr;
                const int col = ks * 16 + 2 * lc;
                a[mi][0] = *(const unsigned*)(As + row * RS + col);
                a[mi][1] = *(const unsigned*)(As + (row + 8) * RS + col);
                a[mi][2] = *(const unsigned*)(As + row * RS + col + 8);
                a[mi][3] = *(const unsigned*)(As + (row + 8) * RS + col + 8);
            }
            #pragma unroll
            for (int ni = 0; ni < 4; ni++) {
                const int n = wn * 32 + ni * 8 + lr;
                const int kk = ks * 16 + 2 * lc;
                b[ni][0] = *(const unsigned*)(Bs + n * RS + kk);
                b[ni][1] = *(const unsigned*)(Bs + n * RS + kk + 8);
            }
            #pragma unroll
            for (int mi = 0; mi < 2; mi++)
                #pragma unroll
                for (int ni = 0; ni < 4; ni++)
                    MMA_F16(acc[mi][ni], a[mi], b[ni]);
        }

        if (j + 3 < NKT) cpaB(j + 3);
        CP_COMMIT;                       // empty group at tail keeps counts uniform
        if (j + 1 < NKT) {
            stsA((j + 1) & 1, v0, v1);   // safe: barrier above ended all reads of this buf
            if (j + 2 < NKT) ldgA(j + 2, v0, v1);
        }
    }

    // epilogue: fp32 store, rna-rounded to tf32 (attn consumes via tf32 mma)
    #pragma unroll
    for (int mi = 0; mi < 2; mi++) {
        const int row0 = m0 + wm * 32 + mi * 16 + lr;
        #pragma unroll
        for (int ni = 0; ni < 4; ni++) {
            const int col = wn * 32 + ni * 8 + 2 * lc;
            float* o1 = out + (size_t)row0 * HS_ + col;
            float* o2 = out + (size_t)(row0 + 8) * HS_ + col;
            o1[0] = __uint_as_float(f2tf32(acc[mi][ni][0]));
            o1[1] = __uint_as_float(f2tf32(acc[mi][ni][1]));
            o2[0] = __uint_as_float(f2tf32(acc[mi][ni][2]));
            o2[1] = __uint_as_float(f2tf32(acc[mi][ni][3]));
        }
    }
}

// ----------------------------------------------------------------------------
// Attention (unchanged from R4): flash-style, tf32 tensor-core S and PV.
// ----------------------------------------------------------------------------
__global__ __launch_bounds__(256, 2) void attn_kernel(float* __restrict__ out)
{
    extern __shared__ float sm[];
    float* sc    = sm;                  // [64][68]
    float* kt    = sm + 64 * 68;        // [64][132]
    float* qv    = kt + 64 * 132;       // [64][132]
    float* f_row = qv + 64 * 132;       // [64]
    float* l_row = f_row + 64;          // [64]

    const int b  = blockIdx.y;
    const int bt = blockIdx.x;
    const int tid = threadIdx.x;
    const int warp = tid >> 5, lane = tid & 31;
    const int band = (warp & 3) * 16;
    const int half = warp >> 2;
    const int lr = lane >> 2, lc = lane & 3;
    const int t0 = bt * 64;
    const float scale = rsqrtf((float)C_);

    for (int i = tid; i < 64 * 32; i += 256) {
        int r = i >> 5, c4 = i & 31;
        float4 v = *(const float4*)(g_k + ((size_t)(b * T_ + t0 + r)) * HS_ + c4 * 4);
        *(float4*)(kt + r * 132 + c4 * 4) = v;
    }

    float m_r[8], l_r[8];
    float oacc[8][4] = {};
    #pragma unroll
    for (int i = 0; i < 8; i++) { m_r[i] = -INFINITY; l_r[i] = 0.f; }

    const int n_stiles = bt + 1;
    for (int st = 0; st < n_stiles; st++) {
        const int s0 = st * 64;

        for (int i = tid; i < 64 * 32; i += 256) {
            int r = i >> 5, c4 = i & 31;
            float4 v = *(const float4*)(g_q + ((size_t)(b * T_ + s0 + r)) * HS_ + c4 * 4);
            *(float4*)(qv + r * 132 + c4 * 4) = v;
        }
        __syncthreads();

        float sacc[4][4] = {};
        #pragma unroll
        for (int kk = 0; kk < 16; kk++) {
            unsigned a[4];
            const int arow = band + lr, acol = kk * 8 + lc;
            a[0] = __float_as_uint(kt[arow * 132 + acol]);
            a[1] = __float_as_uint(kt[(arow + 8) * 132 + acol]);
            a[2] = __float_as_uint(kt[arow * 132 + acol + 4]);
            a[3] = __float_as_uint(kt[(arow + 8) * 132 + acol + 4]);
            #pragma unroll
            for (int nt = 0; nt < 4; nt++) {
                unsigned bb[2];
                const int srow = half * 32 + nt * 8 + lr;
                bb[0] = __float_as_uint(qv[srow * 132 + acol]);
                bb[1] = __float_as_uint(qv[srow * 132 + acol + 4]);
                MMA_TF32(sacc[nt], a, bb);
            }
        }
        const bool diag = (st == bt);
        #pragma unroll
        for (int nt = 0; nt < 4; nt++) {
            const int row = band + lr, col = half * 32 + nt * 8 + 2 * lc;
            const int tg = t0 + row, sg = s0 + col;
            sc[row * 68 + col]           = (!diag || sg     <= tg)     ? sacc[nt][0] * scale : -INFINITY;
            sc[row * 68 + col + 1]       = (!diag || sg + 1 <= tg)     ? sacc[nt][1] * scale : -INFINITY;
            sc[(row + 8) * 68 + col]     = (!diag || sg     <= tg + 8) ? sacc[nt][2] * scale : -INFINITY;
            sc[(row + 8) * 68 + col + 1] = (!diag || sg + 1 <= tg + 8) ? sacc[nt][3] * scale : -INFINITY;
        }
        __syncthreads();

        for (int i = tid; i < 64 * 32; i += 256) {
            int r = i >> 5, c4 = i & 31;
            float4 v = *(const float4*)(g_v + ((size_t)(b * T_ + s0 + r)) * HS_ + c4 * 4);
            *(float4*)(qv + r * 132 + c4 * 4) = v;
        }

        #pragma unroll
        for (int i = 0; i < 8; i++) {
            float* prow = sc + (warp * 8 + i) * 68;
            float s1 = prow[lane], s2 = prow[lane + 32];
            float mt = fmaxf(s1, s2);
            #pragma unroll
            for (int o = 16; o; o >>= 1) mt = fmaxf(mt, __shfl_xor_sync(0xffffffffu, mt, o));
            float mn = fmaxf(m_r[i], mt);
            float f = __expf(m_r[i] - mn);
            float e1 = __uint_as_float(f2tf32(__expf(s1 - mn)));
            float e2 = __uint_as_float(f2tf32(__expf(s2 - mn)));
            prow[lane] = e1; prow[lane + 32] = e2;
            float sum = e1 + e2;
            #pragma unroll
            for (int o = 16; o; o >>= 1) sum += __shfl_xor_sync(0xffffffffu, sum, o);
            l_r[i] = l_r[i] * f + sum;
            m_r[i] = mn;
            if (lane == 0) f_row[warp * 8 + i] = f;
        }
        __syncthreads();

        {
            const float f1 = f_row[band + lr], f2 = f_row[band + lr + 8];
            #pragma unroll
            for (int nt = 0; nt < 8; nt++) {
                oacc[nt][0] *= f1; oacc[nt][1] *= f1;
                oacc[nt][2] *= f2; oacc[nt][3] *= f2;
            }
        }

        #pragma unroll
        for (int kk = 0; kk < 8; kk++) {
            unsigned a[4];
            const int arow = band + lr, acol = kk * 8 + lc;
            a[0] = __float_as_uint(sc[arow * 68 + acol]);
            a[1] = __float_as_uint(sc[(arow + 8) * 68 + acol]);
            a[2] = __float_as_uint(sc[arow * 68 + acol + 4]);
            a[3] = __float_as_uint(sc[(arow + 8) * 68 + acol + 4]);
            #pragma unroll
            for (int nt = 0; nt < 8; nt++) {
                unsigned bb[2];
                const int hcol = half * 64 + nt * 8 + lr;
                bb[0] = __float_as_uint(qv[(kk * 8 + lc) * 132 + hcol]);
                bb[1] = __float_as_uint(qv[(kk * 8 + lc + 4) * 132 + hcol]);
                MMA_TF32(oacc[nt], a, bb);
            }
        }
        __syncthreads();
    }

    if (lane == 0) {
        #pragma unroll
        for (int i = 0; i < 8; i++) l_row[warp * 8 + i] = l_r[i];
    }
    __syncthreads();

    {
        const float inv1 = 1.f / l_row[band + lr];
        const float inv2 = 1.f / l_row[band + lr + 8];
        const size_t r1 = (size_t)(b * T_ + t0 + band + lr) * HS_;
        const size_t r2 = (size_t)(b * T_ + t0 + band + lr + 8) * HS_;
        #pragma unroll
        for (int nt = 0; nt < 8; nt++) {
            const int col = half * 64 + nt * 8 + 2 * lc;
            *(float2*)(out + r1 + col) = make_float2(oacc[nt][0] * inv1, oacc[nt][1] * inv1);
            *(float2*)(out + r2 + col) = make_float2(oacc[nt][2] * inv2, oacc[nt][3] * inv2);
        }
    }
}

// ----------------------------------------------------------------------------
extern "C" void kernel_launch(void* const* d_in, const int* in_sizes, int n_in,
                              void* d_out, int out_size)
{
    (void)in_sizes; (void)n_in; (void)out_size;
    const float* x  = (const float*)d_in[0];
    const float* Wk = (const float*)d_in[1];
    const float* Wq = (const float*)d_in[2];
    const float* Wv = (const float*)d_in[3];

    prep_wt<<<dim3(C_ / 32, HS_ / 32, 3), 256>>>(Wk, Wq, Wv);

    const int psmem = (2 * ABUF + 4 * BBUF) * (int)sizeof(__half);  // 61440 B
    cudaFuncSetAttribute(proj_kernel, cudaFuncAttributeMaxDynamicSharedMemorySize, psmem);
    proj_kernel<<<dim3(3, 128), 512, psmem>>>(x);

    const int asmem = (64 * 68 + 2 * 64 * 132 + 128) * (int)sizeof(float);  // 85504 B
    cudaFuncSetAttribute(attn_kernel, cudaFuncAttributeMaxDynamicSharedMemorySize, asmem);
    attn_kernel<<<dim3(4, 64), 256, asmem>>>((float*)d_out);
}

// round 6
// speedup vs baseline: 3.2362x; 1.1153x over previous
#include <cuda_runtime.h>
#include <cuda_fp16.h>
#include <cstdint>

#define B_  64
#define T_  256
#define C_  2048
#define HS_ 128
#define M_  (B_ * T_)

// Scratch (no cudaMalloc allowed)
__device__ float  g_k[M_ * HS_];
__device__ float  g_q[M_ * HS_];
__device__ float  g_v[M_ * HS_];
__device__ __half g_wh[3 * HS_ * C_];   // [384][2048] fp16 RNE, K-major

__device__ __forceinline__ unsigned f2tf32(float f) {
    unsigned r;
    asm("cvt.rna.tf32.f32 %0, %1;" : "=r"(r) : "f"(f));
    return r;
}
__device__ __forceinline__ void cpa16(void* dst_smem, const void* src_gmem) {
    unsigned d = (unsigned)__cvta_generic_to_shared(dst_smem);
    asm volatile("cp.async.cg.shared.global [%0], [%1], 16;" :: "r"(d), "l"(src_gmem));
}
#define CP_COMMIT  asm volatile("cp.async.commit_group;")
#define CP_WAIT(n) asm volatile("cp.async.wait_group %0;" :: "n"(n))

#define MMA_TF32(acc, a, b)                                                     \
    asm volatile(                                                               \
        "mma.sync.aligned.m16n8k8.row.col.f32.tf32.tf32.f32 "                   \
        "{%0,%1,%2,%3}, {%4,%5,%6,%7}, {%8,%9}, {%0,%1,%2,%3};"                 \
        : "+f"((acc)[0]), "+f"((acc)[1]), "+f"((acc)[2]), "+f"((acc)[3])        \
        : "r"((a)[0]), "r"((a)[1]), "r"((a)[2]), "r"((a)[3]),                   \
          "r"((b)[0]), "r"((b)[1]))

#define MMA_F16(acc, a, b0, b1)                                                 \
    asm volatile(                                                               \
        "mma.sync.aligned.m16n8k16.row.col.f32.f16.f16.f32 "                    \
        "{%0,%1,%2,%3}, {%4,%5,%6,%7}, {%8,%9}, {%0,%1,%2,%3};"                 \
        : "+f"((acc)[0]), "+f"((acc)[1]), "+f"((acc)[2]), "+f"((acc)[3])        \
        : "r"((a)[0]), "r"((a)[1]), "r"((a)[2]), "r"((a)[3]),                   \
          "r"(b0), "r"(b1))

#define LDSM_X4(r0, r1, r2, r3, addr)                                           \
    asm volatile("ldmatrix.sync.aligned.m8n8.x4.shared.b16 {%0,%1,%2,%3}, [%4];"\
        : "=r"(r0), "=r"(r1), "=r"(r2), "=r"(r3) : "r"(addr))

// ----------------------------------------------------------------------------
// Prep: g_wh[p*128 + n][k] = fp16_rn(W_p[k][n])
// ----------------------------------------------------------------------------
__global__ void prep_wt(const float* __restrict__ Wk, const float* __restrict__ Wq,
                        const float* __restrict__ Wv)
{
    __shared__ float t[32][33];
    const float* W = blockIdx.z == 0 ? Wk : (blockIdx.z == 1 ? Wq : Wv);
    const int k0 = blockIdx.x * 32, n0 = blockIdx.y * 32;
    const int tx = threadIdx.x & 31, ty = threadIdx.x >> 5;
    #pragma unroll
    for (int i = 0; i < 32; i += 8)
        t[ty + i][tx] = W[(size_t)(k0 + ty + i) * HS_ + n0 + tx];
    __syncthreads();
    #pragma unroll
    for (int i = 0; i < 32; i += 8)
        g_wh[((size_t)blockIdx.z * HS_ + n0 + ty + i) * C_ + k0 + tx] =
            __float2half_rn(t[tx][ty + i]);
}

// ----------------------------------------------------------------------------
// Fused projection GEMM (fp16 mma m16n8k16): [16384,2048] @ [2048,384].
// Grid 128 (single wave), 512 threads, block tile 128 x 384 x BK32.
// Warp grid 4m x 4n, warp tile 32 x 96. A fp32 via cp.async (cvt at frag load),
// B fp16 via cp.async + ldmatrix. 3-stage pipeline.
// ----------------------------------------------------------------------------
#define NF   384
#define NKT  (C_ / 32)          // 64
#define RSA  36                  // A row stride (floats)
#define RSB  40                  // B row stride (halves)
#define ASTG (128 * RSA)         // floats / stage
#define BSTG (NF * RSB)          // halves / stage
#define PSMEM (3 * (ASTG * 4 + BSTG * 2))   // 147456 B

__global__ __launch_bounds__(512, 1) void proj_kernel(const float* __restrict__ x)
{
    extern __shared__ char smraw[];
    float*  As = (float*)smraw;                        // 3 stages
    __half* Bs = (__half*)(smraw + 3 * ASTG * 4);      // 3 stages
    const uint32_t Bs_u = (uint32_t)__cvta_generic_to_shared(Bs);

    const int tid  = threadIdx.x;
    const int warp = tid >> 5, lane = tid & 31;
    const int wm = warp >> 2, wn = warp & 3;           // 4x4 warps
    const int lr = lane >> 2, lc = lane & 3;
    const int m0 = blockIdx.x * 128;

    // ldmatrix lane base (halves): rows wn*96 + (lane&15), k-half (lane>>4)*8
    const int bln = (wn * 96 + (lane & 15)) * RSB + (lane >> 4) * 8;

    auto load_tile = [&](int s, int j) {
        float*  Ad = As + s * ASTG;
        __half* Bd = Bs + s * BSTG;
        const int k0 = j * 32;
        #pragma unroll
        for (int i = 0; i < 2; i++) {                  // A: 1024 chunks
            int c = tid + i * 512, r = c >> 3, q = c & 7;
            cpa16(Ad + r * RSA + q * 4, x + (size_t)(m0 + r) * C_ + k0 + q * 4);
        }
        #pragma unroll
        for (int i = 0; i < 3; i++) {                  // B: 1536 chunks
            int c = tid + i * 512, r = c >> 2, q = c & 3;
            cpa16(Bd + r * RSB + q * 8, g_wh + (size_t)r * C_ + k0 + q * 8);
        }
        CP_COMMIT;
    };

    load_tile(0, 0);
    load_tile(1, 1);

    float acc[2][12][4] = {};

    for (int j = 0; j < NKT; j++) {
        if (j < NKT - 2) { CP_WAIT(1); } else { CP_WAIT(0); }
        __syncthreads();

        const float*   Aj  = As + (j % 3) * ASTG;
        const uint32_t Bju = Bs_u + (uint32_t)((j % 3) * BSTG) * 2;

        #pragma unroll
        for (int ks = 0; ks < 2; ks++) {
            const int kb = ks * 16;
            unsigned a[2][4];
            #pragma unroll
            for (int mi = 0; mi < 2; mi++) {
                const int row = wm * 32 + mi * 16 + lr;
                float2 f0 = *(const float2*)(Aj + row * RSA + kb + 2 * lc);
                float2 f1 = *(const float2*)(Aj + (row + 8) * RSA + kb + 2 * lc);
                float2 f2 = *(const float2*)(Aj + row * RSA + kb + 2 * lc + 8);
                float2 f3 = *(const float2*)(Aj + (row + 8) * RSA + kb + 2 * lc + 8);
                __half2 h0 = __floats2half2_rn(f0.x, f0.y);
                __half2 h1 = __floats2half2_rn(f1.x, f1.y);
                __half2 h2 = __floats2half2_rn(f2.x, f2.y);
                __half2 h3 = __floats2half2_rn(f3.x, f3.y);
                a[mi][0] = *reinterpret_cast<unsigned*>(&h0);
                a[mi][1] = *reinterpret_cast<unsigned*>(&h1);
                a[mi][2] = *reinterpret_cast<unsigned*>(&h2);
                a[mi][3] = *reinterpret_cast<unsigned*>(&h3);
            }
            #pragma unroll
            for (int pr = 0; pr < 6; pr++) {
                unsigned b0, b1, b2, b3;   // b[2pr][0], b[2pr+1][0], b[2pr][1], b[2pr+1][1]
                LDSM_X4(b0, b1, b2, b3,
                        Bju + (uint32_t)(bln + pr * 16 * RSB + kb) * 2);
                MMA_F16(acc[0][2 * pr],     a[0], b0, b2);
                MMA_F16(acc[0][2 * pr + 1], a[0], b1, b3);
                MMA_F16(acc[1][2 * pr],     a[1], b0, b2);
                MMA_F16(acc[1][2 * pr + 1], a[1], b1, b3);
            }
        }

        if (j + 2 < NKT) load_tile((j + 2) % 3, j + 2);
    }

    // epilogue: split N=384 into the 3 outputs, rna-round to tf32 for attn
    float* const outp[3] = { g_k, g_q, g_v };
    #pragma unroll
    for (int mi = 0; mi < 2; mi++) {
        const int row0 = m0 + wm * 32 + mi * 16 + lr;
        #pragma unroll
        for (int ni = 0; ni < 12; ni++) {
            const int gcol = wn * 96 + ni * 8;
            float* o = outp[gcol >> 7];
            const int col = (gcol & 127) + 2 * lc;
            float* o1 = o + (size_t)row0 * HS_ + col;
            float* o2 = o + (size_t)(row0 + 8) * HS_ + col;
            o1[0] = __uint_as_float(f2tf32(acc[mi][ni][0]));
            o1[1] = __uint_as_float(f2tf32(acc[mi][ni][1]));
            o2[0] = __uint_as_float(f2tf32(acc[mi][ni][2]));
            o2[1] = __uint_as_float(f2tf32(acc[mi][ni][3]));
        }
    }
}

// ----------------------------------------------------------------------------
// Attention (unchanged from R4/R5): flash-style, tf32 tensor-core S and PV.
// ----------------------------------------------------------------------------
__global__ __launch_bounds__(256, 2) void attn_kernel(float* __restrict__ out)
{
    extern __shared__ float sm[];
    float* sc    = sm;                  // [64][68]
    float* kt    = sm + 64 * 68;        // [64][132]
    float* qv    = kt + 64 * 132;       // [64][132]
    float* f_row = qv + 64 * 132;       // [64]
    float* l_row = f_row + 64;          // [64]

    const int b  = blockIdx.y;
    const int bt = blockIdx.x;
    const int tid = threadIdx.x;
    const int warp = tid >> 5, lane = tid & 31;
    const int band = (warp & 3) * 16;
    const int half = warp >> 2;
    const int lr = lane >> 2, lc = lane & 3;
    const int t0 = bt * 64;
    const float scale = rsqrtf((float)C_);

    for (int i = tid; i < 64 * 32; i += 256) {
        int r = i >> 5, c4 = i & 31;
        float4 v = *(const float4*)(g_k + ((size_t)(b * T_ + t0 + r)) * HS_ + c4 * 4);
        *(float4*)(kt + r * 132 + c4 * 4) = v;
    }

    float m_r[8], l_r[8];
    float oacc[8][4] = {};
    #pragma unroll
    for (int i = 0; i < 8; i++) { m_r[i] = -INFINITY; l_r[i] = 0.f; }

    const int n_stiles = bt + 1;
    for (int st = 0; st < n_stiles; st++) {
        const int s0 = st * 64;

        for (int i = tid; i < 64 * 32; i += 256) {
            int r = i >> 5, c4 = i & 31;
            float4 v = *(const float4*)(g_q + ((size_t)(b * T_ + s0 + r)) * HS_ + c4 * 4);
            *(float4*)(qv + r * 132 + c4 * 4) = v;
        }
        __syncthreads();

        float sacc[4][4] = {};
        #pragma unroll
        for (int kk = 0; kk < 16; kk++) {
            unsigned a[4];
            const int arow = band + lr, acol = kk * 8 + lc;
            a[0] = __float_as_uint(kt[arow * 132 + acol]);
            a[1] = __float_as_uint(kt[(arow + 8) * 132 + acol]);
            a[2] = __float_as_uint(kt[arow * 132 + acol + 4]);
            a[3] = __float_as_uint(kt[(arow + 8) * 132 + acol + 4]);
            #pragma unroll
            for (int nt = 0; nt < 4; nt++) {
                unsigned bb[2];
                const int srow = half * 32 + nt * 8 + lr;
                bb[0] = __float_as_uint(qv[srow * 132 + acol]);
                bb[1] = __float_as_uint(qv[srow * 132 + acol + 4]);
                MMA_TF32(sacc[nt], a, bb);
            }
        }
        const bool diag = (st == bt);
        #pragma unroll
        for (int nt = 0; nt < 4; nt++) {
            const int row = band + lr, col = half * 32 + nt * 8 + 2 * lc;
            const int tg = t0 + row, sg = s0 + col;
            sc[row * 68 + col]           = (!diag || sg     <= tg)     ? sacc[nt][0] * scale : -INFINITY;
            sc[row * 68 + col + 1]       = (!diag || sg + 1 <= tg)     ? sacc[nt][1] * scale : -INFINITY;
            sc[(row + 8) * 68 + col]     = (!diag || sg     <= tg + 8) ? sacc[nt][2] * scale : -INFINITY;
            sc[(row + 8) * 68 + col + 1] = (!diag || sg + 1 <= tg + 8) ? sacc[nt][3] * scale : -INFINITY;
        }
        __syncthreads();

        for (int i = tid; i < 64 * 32; i += 256) {
            int r = i >> 5, c4 = i & 31;
            float4 v = *(const float4*)(g_v + ((size_t)(b * T_ + s0 + r)) * HS_ + c4 * 4);
            *(float4*)(qv + r * 132 + c4 * 4) = v;
        }

        #pragma unroll
        for (int i = 0; i < 8; i++) {
            float* prow = sc + (warp * 8 + i) * 68;
            float s1 = prow[lane], s2 = prow[lane + 32];
            float mt = fmaxf(s1, s2);
            #pragma unroll
            for (int o = 16; o; o >>= 1) mt = fmaxf(mt, __shfl_xor_sync(0xffffffffu, mt, o));
            float mn = fmaxf(m_r[i], mt);
            float f = __expf(m_r[i] - mn);
            float e1 = __uint_as_float(f2tf32(__expf(s1 - mn)));
            float e2 = __uint_as_float(f2tf32(__expf(s2 - mn)));
            prow[lane] = e1; prow[lane + 32] = e2;
            float sum = e1 + e2;
            #pragma unroll
            for (int o = 16; o; o >>= 1) sum += __shfl_xor_sync(0xffffffffu, sum, o);
            l_r[i] = l_r[i] * f + sum;
            m_r[i] = mn;
            if (lane == 0) f_row[warp * 8 + i] = f;
        }
        __syncthreads();

        {
            const float f1 = f_row[band + lr], f2 = f_row[band + lr + 8];
            #pragma unroll
            for (int nt = 0; nt < 8; nt++) {
                oacc[nt][0] *= f1; oacc[nt][1] *= f1;
                oacc[nt][2] *= f2; oacc[nt][3] *= f2;
            }
        }

        #pragma unroll
        for (int kk = 0; kk < 8; kk++) {
            unsigned a[4];
            const int arow = band + lr, acol = kk * 8 + lc;
            a[0] = __float_as_uint(sc[arow * 68 + acol]);
            a[1] = __float_as_uint(sc[(arow + 8) * 68 + acol]);
            a[2] = __float_as_uint(sc[arow * 68 + acol + 4]);
            a[3] = __float_as_uint(sc[(arow + 8) * 68 + acol + 4]);
            #pragma unroll
            for (int nt = 0; nt < 8; nt++) {
                unsigned bb[2];
                const int hcol = half * 64 + nt * 8 + lr;
                bb[0] = __float_as_uint(qv[(kk * 8 + lc) * 132 + hcol]);
                bb[1] = __float_as_uint(qv[(kk * 8 + lc + 4) * 132 + hcol]);
                MMA_TF32(oacc[nt], a, bb);
            }
        }
        __syncthreads();
    }

    if (lane == 0) {
        #pragma unroll
        for (int i = 0; i < 8; i++) l_row[warp * 8 + i] = l_r[i];
    }
    __syncthreads();

    {
        const float inv1 = 1.f / l_row[band + lr];
        const float inv2 = 1.f / l_row[band + lr + 8];
        const size_t r1 = (size_t)(b * T_ + t0 + band + lr) * HS_;
        const size_t r2 = (size_t)(b * T_ + t0 + band + lr + 8) * HS_;
        #pragma unroll
        for (int nt = 0; nt < 8; nt++) {
            const int col = half * 64 + nt * 8 + 2 * lc;
            *(float2*)(out + r1 + col) = make_float2(oacc[nt][0] * inv1, oacc[nt][1] * inv1);
            *(float2*)(out + r2 + col) = make_float2(oacc[nt][2] * inv2, oacc[nt][3] * inv2);
        }
    }
}

// ----------------------------------------------------------------------------
extern "C" void kernel_launch(void* const* d_in, const int* in_sizes, int n_in,
                              void* d_out, int out_size)
{
    (void)in_sizes; (void)n_in; (void)out_size;
    const float* x  = (const float*)d_in[0];
    const float* Wk = (const float*)d_in[1];
    const float* Wq = (const float*)d_in[2];
    const float* Wv = (const float*)d_in[3];

    prep_wt<<<dim3(C_ / 32, HS_ / 32, 3), 256>>>(Wk, Wq, Wv);

    cudaFuncSetAttribute(proj_kernel, cudaFuncAttributeMaxDynamicSharedMemorySize, PSMEM);
    proj_kernel<<<M_ / 128, 512, PSMEM>>>(x);

    const int asmem = (64 * 68 + 2 * 64 * 132 + 128) * (int)sizeof(float);
    cudaFuncSetAttribute(attn_kernel, cudaFuncAttributeMaxDynamicSharedMemorySize, asmem);
    attn_kernel<<<dim3(4, 64), 256, asmem>>>((float*)d_out);
}

// round 7
// speedup vs baseline: 3.5890x; 1.1090x over previous
#include <cuda_runtime.h>
#include <cuda_fp16.h>
#include <cstdint>

#define B_  64
#define T_  256
#define C_  2048
#define HS_ 128
#define M_  (B_ * T_)

// Scratch (no cudaMalloc allowed)
__device__ __half g_k[M_ * HS_];
__device__ __half g_q[M_ * HS_];
__device__ __half g_v[M_ * HS_];
__device__ __half g_wh[3 * HS_ * C_];   // [384][2048] fp16 RNE, K-major

__device__ __forceinline__ void cpa16(void* dst_smem, const void* src_gmem) {
    unsigned d = (unsigned)__cvta_generic_to_shared(dst_smem);
    asm volatile("cp.async.cg.shared.global [%0], [%1], 16;" :: "r"(d), "l"(src_gmem));
}
#define CP_COMMIT  asm volatile("cp.async.commit_group;")
#define CP_WAIT(n) asm volatile("cp.async.wait_group %0;" :: "n"(n))

#define MMA_F16(acc, a, b0, b1)                                                 \
    asm volatile(                                                               \
        "mma.sync.aligned.m16n8k16.row.col.f32.f16.f16.f32 "                    \
        "{%0,%1,%2,%3}, {%4,%5,%6,%7}, {%8,%9}, {%0,%1,%2,%3};"                 \
        : "+f"((acc)[0]), "+f"((acc)[1]), "+f"((acc)[2]), "+f"((acc)[3])        \
        : "r"((a)[0]), "r"((a)[1]), "r"((a)[2]), "r"((a)[3]),                   \
          "r"(b0), "r"(b1))

#define LDSM_X4(r0, r1, r2, r3, addr)                                           \
    asm volatile("ldmatrix.sync.aligned.m8n8.x4.shared.b16 {%0,%1,%2,%3}, [%4];"\
        : "=r"(r0), "=r"(r1), "=r"(r2), "=r"(r3) : "r"(addr))

#define LDSM_X4_T(r0, r1, r2, r3, addr)                                         \
    asm volatile("ldmatrix.sync.aligned.m8n8.x4.trans.shared.b16 {%0,%1,%2,%3}, [%4];"\
        : "=r"(r0), "=r"(r1), "=r"(r2), "=r"(r3) : "r"(addr))

// ----------------------------------------------------------------------------
// Prep: g_wh[p*128 + n][k] = fp16_rn(W_p[k][n])
// ----------------------------------------------------------------------------
__global__ void prep_wt(const float* __restrict__ Wk, const float* __restrict__ Wq,
                        const float* __restrict__ Wv)
{
    __shared__ float t[32][33];
    const float* W = blockIdx.z == 0 ? Wk : (blockIdx.z == 1 ? Wq : Wv);
    const int k0 = blockIdx.x * 32, n0 = blockIdx.y * 32;
    const int tx = threadIdx.x & 31, ty = threadIdx.x >> 5;
    #pragma unroll
    for (int i = 0; i < 32; i += 8)
        t[ty + i][tx] = W[(size_t)(k0 + ty + i) * HS_ + n0 + tx];
    __syncthreads();
    #pragma unroll
    for (int i = 0; i < 32; i += 8)
        g_wh[((size_t)blockIdx.z * HS_ + n0 + ty + i) * C_ + k0 + tx] =
            __float2half_rn(t[tx][ty + i]);
}

// ----------------------------------------------------------------------------
// Fused projection GEMM (fp16 mma m16n8k16): [16384,2048] @ [2048,384].
// Grid 128 (single wave), 512 threads, block tile 128 x 384 x BK32.
// Outputs written as fp16 to g_k/g_q/g_v.
// ----------------------------------------------------------------------------
#define NF   384
#define NKT  (C_ / 32)          // 64
#define RSA  36                  // A row stride (floats)
#define RSB  40                  // B row stride (halves)
#define ASTG (128 * RSA)
#define BSTG (NF * RSB)
#define PSMEM (3 * (ASTG * 4 + BSTG * 2))   // 147456 B

__global__ __launch_bounds__(512, 1) void proj_kernel(const float* __restrict__ x)
{
    extern __shared__ char smraw[];
    float*  As = (float*)smraw;
    __half* Bs = (__half*)(smraw + 3 * ASTG * 4);
    const uint32_t Bs_u = (uint32_t)__cvta_generic_to_shared(Bs);

    const int tid  = threadIdx.x;
    const int warp = tid >> 5, lane = tid & 31;
    const int wm = warp >> 2, wn = warp & 3;
    const int lr = lane >> 2, lc = lane & 3;
    const int m0 = blockIdx.x * 128;

    const int bln = (wn * 96 + (lane & 15)) * RSB + (lane >> 4) * 8;

    auto load_tile = [&](int s, int j) {
        float*  Ad = As + s * ASTG;
        __half* Bd = Bs + s * BSTG;
        const int k0 = j * 32;
        #pragma unroll
        for (int i = 0; i < 2; i++) {
            int c = tid + i * 512, r = c >> 3, q = c & 7;
            cpa16(Ad + r * RSA + q * 4, x + (size_t)(m0 + r) * C_ + k0 + q * 4);
        }
        #pragma unroll
        for (int i = 0; i < 3; i++) {
            int c = tid + i * 512, r = c >> 2, q = c & 3;
            cpa16(Bd + r * RSB + q * 8, g_wh + (size_t)r * C_ + k0 + q * 8);
        }
        CP_COMMIT;
    };

    load_tile(0, 0);
    load_tile(1, 1);

    float acc[2][12][4] = {};

    for (int j = 0; j < NKT; j++) {
        if (j < NKT - 2) { CP_WAIT(1); } else { CP_WAIT(0); }
        __syncthreads();

        const float*   Aj  = As + (j % 3) * ASTG;
        const uint32_t Bju = Bs_u + (uint32_t)((j % 3) * BSTG) * 2;

        #pragma unroll
        for (int ks = 0; ks < 2; ks++) {
            const int kb = ks * 16;
            unsigned a[2][4];
            #pragma unroll
            for (int mi = 0; mi < 2; mi++) {
                const int row = wm * 32 + mi * 16 + lr;
                float2 f0 = *(const float2*)(Aj + row * RSA + kb + 2 * lc);
                float2 f1 = *(const float2*)(Aj + (row + 8) * RSA + kb + 2 * lc);
                float2 f2 = *(const float2*)(Aj + row * RSA + kb + 2 * lc + 8);
                float2 f3 = *(const float2*)(Aj + (row + 8) * RSA + kb + 2 * lc + 8);
                __half2 h0 = __floats2half2_rn(f0.x, f0.y);
                __half2 h1 = __floats2half2_rn(f1.x, f1.y);
                __half2 h2 = __floats2half2_rn(f2.x, f2.y);
                __half2 h3 = __floats2half2_rn(f3.x, f3.y);
                a[mi][0] = *reinterpret_cast<unsigned*>(&h0);
                a[mi][1] = *reinterpret_cast<unsigned*>(&h1);
                a[mi][2] = *reinterpret_cast<unsigned*>(&h2);
                a[mi][3] = *reinterpret_cast<unsigned*>(&h3);
            }
            #pragma unroll
            for (int pr = 0; pr < 6; pr++) {
                unsigned b0, b1, b2, b3;
                LDSM_X4(b0, b1, b2, b3,
                        Bju + (uint32_t)(bln + pr * 16 * RSB + kb) * 2);
                MMA_F16(acc[0][2 * pr],     a[0], b0, b2);
                MMA_F16(acc[0][2 * pr + 1], a[0], b1, b3);
                MMA_F16(acc[1][2 * pr],     a[1], b0, b2);
                MMA_F16(acc[1][2 * pr + 1], a[1], b1, b3);
            }
        }

        if (j + 2 < NKT) load_tile((j + 2) % 3, j + 2);
    }

    // epilogue: fp16 outputs
    __half* const outp[3] = { g_k, g_q, g_v };
    #pragma unroll
    for (int mi = 0; mi < 2; mi++) {
        const int row0 = m0 + wm * 32 + mi * 16 + lr;
        #pragma unroll
        for (int ni = 0; ni < 12; ni++) {
            const int gcol = wn * 96 + ni * 8;
            __half* o = outp[gcol >> 7];
            const int col = (gcol & 127) + 2 * lc;
            __half2 h1 = __floats2half2_rn(acc[mi][ni][0], acc[mi][ni][1]);
            __half2 h2 = __floats2half2_rn(acc[mi][ni][2], acc[mi][ni][3]);
            *(__half2*)(o + (size_t)row0 * HS_ + col)       = h1;
            *(__half2*)(o + (size_t)(row0 + 8) * HS_ + col) = h2;
        }
    }
}

// ----------------------------------------------------------------------------
// Attention: flash-style, fp16 mma m16n8k16 for S and PV, ldmatrix frags.
// Block (bt,b): 64 t-rows. Warp w: rows band=(w&3)*16, col half=(w>>2).
// smem: sc f32[64][68] | f_row,l_row | ph h[64][72] | kt,qv h[64][136] = 62 KB.
// ----------------------------------------------------------------------------
__global__ __launch_bounds__(256, 2) void attn_kernel(float* __restrict__ out)
{
    extern __shared__ char smr[];
    float*  sc    = (float*)smr;                   // [64][68]
    float*  f_row = sc + 64 * 68;                  // [64]
    float*  l_row = f_row + 64;                    // [64]
    __half* ph    = (__half*)(l_row + 64);         // [64][72]
    __half* kt    = ph + 64 * 72;                  // [64][136]
    __half* qv    = kt + 64 * 136;                 // [64][136]
    const uint32_t ph_u = (uint32_t)__cvta_generic_to_shared(ph);
    const uint32_t kt_u = (uint32_t)__cvta_generic_to_shared(kt);
    const uint32_t qv_u = (uint32_t)__cvta_generic_to_shared(qv);

    const int b  = blockIdx.y;
    const int bt = blockIdx.x;
    const int tid = threadIdx.x;
    const int warp = tid >> 5, lane = tid & 31;
    const int band = (warp & 3) * 16;
    const int hf = warp >> 2;
    const int lr = lane >> 2, lc = lane & 3;
    const int t0 = bt * 64;
    const float scale = rsqrtf((float)C_);

    // ldmatrix lane bases (bytes)
    const uint32_t aK = kt_u + (uint32_t)((band + (lane & 15)) * 136 + (lane >> 4) * 8) * 2;
    const uint32_t bQ = qv_u + (uint32_t)((hf * 32 + (lane & 7) + (lane >> 4) * 8) * 136
                                          + ((lane >> 3) & 1) * 8) * 2;
    const uint32_t aP = ph_u + (uint32_t)((band + (lane & 15)) * 72 + (lane >> 4) * 8) * 2;
    const uint32_t bV = qv_u + (uint32_t)(((lane & 7) + ((lane >> 3) & 1) * 8) * 136
                                          + hf * 64 + (lane >> 4) * 8) * 2;

    // K tile (rows t0..t0+63), fp16, 16B chunks
    for (int i = tid; i < 1024; i += 256) {
        int r = i >> 4, c = i & 15;
        *(uint4*)(kt + r * 136 + c * 8) =
            *(const uint4*)(g_k + (size_t)(b * T_ + t0 + r) * HS_ + c * 8);
    }

    float m_r[8], l_r[8];
    float oacc[8][4] = {};
    #pragma unroll
    for (int i = 0; i < 8; i++) { m_r[i] = -INFINITY; l_r[i] = 0.f; }

    const int n_stiles = bt + 1;
    for (int st = 0; st < n_stiles; st++) {
        const int s0 = st * 64;

        // Q tile
        for (int i = tid; i < 1024; i += 256) {
            int r = i >> 4, c = i & 15;
            *(uint4*)(qv + r * 136 + c * 8) =
                *(const uint4*)(g_q + (size_t)(b * T_ + s0 + r) * HS_ + c * 8);
        }
        __syncthreads();   // (A) kt + qv(Q) ready

        // ---- S = K Q^T : rows band..+15, cols hf*32..+31, k=128 (8 blocks) ----
        float sacc[4][4] = {};
        #pragma unroll
        for (int kk = 0; kk < 8; kk++) {
            unsigned a[4];
            LDSM_X4(a[0], a[1], a[2], a[3], aK + kk * 32);
            unsigned q0, q1, q2, q3, r0, r1, r2, r3;
            LDSM_X4(q0, q1, q2, q3, bQ + kk * 32);                 // n-tiles 0,1
            LDSM_X4(r0, r1, r2, r3, bQ + 16 * 136 * 2 + kk * 32);  // n-tiles 2,3
            MMA_F16(sacc[0], a, q0, q1);
            MMA_F16(sacc[1], a, q2, q3);
            MMA_F16(sacc[2], a, r0, r1);
            MMA_F16(sacc[3], a, r2, r3);
        }
        const bool diag = (st == bt);
        #pragma unroll
        for (int nt = 0; nt < 4; nt++) {
            const int row = band + lr, col = hf * 32 + nt * 8 + 2 * lc;
            const int tg = t0 + row, sg = s0 + col;
            sc[row * 68 + col]           = (!diag || sg     <= tg)     ? sacc[nt][0] * scale : -INFINITY;
            sc[row * 68 + col + 1]       = (!diag || sg + 1 <= tg)     ? sacc[nt][1] * scale : -INFINITY;
            sc[(row + 8) * 68 + col]     = (!diag || sg     <= tg + 8) ? sacc[nt][2] * scale : -INFINITY;
            sc[(row + 8) * 68 + col + 1] = (!diag || sg + 1 <= tg + 8) ? sacc[nt][3] * scale : -INFINITY;
        }
        __syncthreads();   // (B) sc full; qv(Q) reads done

        // V tile (overwrites qv; overlaps softmax)
        for (int i = tid; i < 1024; i += 256) {
            int r = i >> 4, c = i & 15;
            *(uint4*)(qv + r * 136 + c * 8) =
                *(const uint4*)(g_v + (size_t)(b * T_ + s0 + r) * HS_ + c * 8);
        }

        // ---- online softmax: warp owns rows warp*8..+7; P -> ph (fp16) ----
        #pragma unroll
        for (int i = 0; i < 8; i++) {
            const int row = warp * 8 + i;
            float* prow = sc + row * 68;
            float s1 = prow[lane], s2 = prow[lane + 32];
            float mt = fmaxf(s1, s2);
            #pragma unroll
            for (int o = 16; o; o >>= 1) mt = fmaxf(mt, __shfl_xor_sync(0xffffffffu, mt, o));
            float mn = fmaxf(m_r[i], mt);
            float f = __expf(m_r[i] - mn);
            __half e1h = __float2half_rn(__expf(s1 - mn));
            __half e2h = __float2half_rn(__expf(s2 - mn));
            ph[row * 72 + lane]      = e1h;
            ph[row * 72 + lane + 32] = e2h;
            float sum = __half2float(e1h) + __half2float(e2h);
            #pragma unroll
            for (int o = 16; o; o >>= 1) sum += __shfl_xor_sync(0xffffffffu, sum, o);
            l_r[i] = l_r[i] * f + sum;
            m_r[i] = mn;
            if (lane == 0) f_row[row] = f;
        }
        __syncthreads();   // (C) ph + V + f_row ready

        // rescale accumulators
        {
            const float f1 = f_row[band + lr], f2 = f_row[band + lr + 8];
            #pragma unroll
            for (int nt = 0; nt < 8; nt++) {
                oacc[nt][0] *= f1; oacc[nt][1] *= f1;
                oacc[nt][2] *= f2; oacc[nt][3] *= f2;
            }
        }

        // ---- O += P V : rows band..+15, cols hf*64..+63, k=64 (4 blocks) ----
        #pragma unroll
        for (int kk = 0; kk < 4; kk++) {
            unsigned p[4];
            LDSM_X4(p[0], p[1], p[2], p[3], aP + kk * 32);
            #pragma unroll
            for (int np = 0; np < 4; np++) {
                unsigned v0, v1, v2, v3;
                LDSM_X4_T(v0, v1, v2, v3,
                          bV + (uint32_t)(kk * 16 * 136 + np * 16) * 2);
                MMA_F16(oacc[np * 2],     p, v0, v1);
                MMA_F16(oacc[np * 2 + 1], p, v2, v3);
            }
        }
        __syncthreads();   // (D) sc/ph/qv free
    }

    if (lane == 0) {
        #pragma unroll
        for (int i = 0; i < 8; i++) l_row[warp * 8 + i] = l_r[i];
    }
    __syncthreads();

    {
        const float inv1 = 1.f / l_row[band + lr];
        const float inv2 = 1.f / l_row[band + lr + 8];
        const size_t r1 = (size_t)(b * T_ + t0 + band + lr) * HS_;
        const size_t r2 = (size_t)(b * T_ + t0 + band + lr + 8) * HS_;
        #pragma unroll
        for (int nt = 0; nt < 8; nt++) {
            const int col = hf * 64 + nt * 8 + 2 * lc;
            *(float2*)(out + r1 + col) = make_float2(oacc[nt][0] * inv1, oacc[nt][1] * inv1);
            *(float2*)(out + r2 + col) = make_float2(oacc[nt][2] * inv2, oacc[nt][3] * inv2);
        }
    }
}

// ----------------------------------------------------------------------------
extern "C" void kernel_launch(void* const* d_in, const int* in_sizes, int n_in,
                              void* d_out, int out_size)
{
    (void)in_sizes; (void)n_in; (void)out_size;
    const float* x  = (const float*)d_in[0];
    const float* Wk = (const float*)d_in[1];
    const float* Wq = (const float*)d_in[2];
    const float* Wv = (const float*)d_in[3];

    prep_wt<<<dim3(C_ / 32, HS_ / 32, 3), 256>>>(Wk, Wq, Wv);

    cudaFuncSetAttribute(proj_kernel, cudaFuncAttributeMaxDynamicSharedMemorySize, PSMEM);
    proj_kernel<<<M_ / 128, 512, PSMEM>>>(x);

    const int asmem = 64 * 68 * 4 + 128 * 4 + 64 * 72 * 2 + 2 * 64 * 136 * 2;  // 61952
    cudaFuncSetAttribute(attn_kernel, cudaFuncAttributeMaxDynamicSharedMemorySize, asmem);
    attn_kernel<<<dim3(4, 64), 256, asmem>>>((float*)d_out);
}

// round 8
// speedup vs baseline: 3.6953x; 1.0296x over previous
#include <cuda_runtime.h>
#include <cuda_fp16.h>
#include <cstdint>

#define B_  64
#define T_  256
#define C_  2048
#define HS_ 128
#define M_  (B_ * T_)

// Scratch (no cudaMalloc allowed)
__device__ __half g_k[M_ * HS_];
__device__ __half g_q[M_ * HS_];
__device__ __half g_v[M_ * HS_];
__device__ __half g_wh[3 * HS_ * C_];   // [384][2048] fp16 RNE, K-major

__device__ __forceinline__ void cpa16(void* dst_smem, const void* src_gmem) {
    unsigned d = (unsigned)__cvta_generic_to_shared(dst_smem);
    asm volatile("cp.async.cg.shared.global [%0], [%1], 16;" :: "r"(d), "l"(src_gmem));
}
#define CP_COMMIT  asm volatile("cp.async.commit_group;")
#define CP_WAIT(n) asm volatile("cp.async.wait_group %0;" :: "n"(n))

#define MMA_F16(acc, a, b0, b1)                                                 \
    asm volatile(                                                               \
        "mma.sync.aligned.m16n8k16.row.col.f32.f16.f16.f32 "                    \
        "{%0,%1,%2,%3}, {%4,%5,%6,%7}, {%8,%9}, {%0,%1,%2,%3};"                 \
        : "+f"((acc)[0]), "+f"((acc)[1]), "+f"((acc)[2]), "+f"((acc)[3])        \
        : "r"((a)[0]), "r"((a)[1]), "r"((a)[2]), "r"((a)[3]),                   \
          "r"(b0), "r"(b1))

#define LDSM_X4(r0, r1, r2, r3, addr)                                           \
    asm volatile("ldmatrix.sync.aligned.m8n8.x4.shared.b16 {%0,%1,%2,%3}, [%4];"\
        : "=r"(r0), "=r"(r1), "=r"(r2), "=r"(r3) : "r"(addr))

#define LDSM_X4_T(r0, r1, r2, r3, addr)                                         \
    asm volatile("ldmatrix.sync.aligned.m8n8.x4.trans.shared.b16 {%0,%1,%2,%3}, [%4];"\
        : "=r"(r0), "=r"(r1), "=r"(r2), "=r"(r3) : "r"(addr))

// ----------------------------------------------------------------------------
// Prep: g_wh[p*128 + n][k] = fp16_rn(W_p[k][n])
// ----------------------------------------------------------------------------
__global__ void prep_wt(const float* __restrict__ Wk, const float* __restrict__ Wq,
                        const float* __restrict__ Wv)
{
    __shared__ float t[32][33];
    const float* W = blockIdx.z == 0 ? Wk : (blockIdx.z == 1 ? Wq : Wv);
    const int k0 = blockIdx.x * 32, n0 = blockIdx.y * 32;
    const int tx = threadIdx.x & 31, ty = threadIdx.x >> 5;
    #pragma unroll
    for (int i = 0; i < 32; i += 8)
        t[ty + i][tx] = W[(size_t)(k0 + ty + i) * HS_ + n0 + tx];
    __syncthreads();
    #pragma unroll
    for (int i = 0; i < 32; i += 8)
        g_wh[((size_t)blockIdx.z * HS_ + n0 + ty + i) * C_ + k0 + tx] =
            __float2half_rn(t[tx][ty + i]);
}

// ----------------------------------------------------------------------------
// Fused projection GEMM (fp16 mma m16n8k16): [16384,2048] @ [2048,384].
// M-tile 64 -> grid 256, 2 CTA/SM co-resident (bubble filling).
// 256 threads, warp grid 2m x 4n, warp tile 32 x 96. 3-stage cp.async.
// B stored unpadded (64 B rows) with XOR swizzle: chunk c -> c ^ ((row>>1)&3).
// ----------------------------------------------------------------------------
#define NF    384
#define NKT   (C_ / 32)          // 64
#define RSA   36                  // A row stride (floats)
#define ASTGF (64 * RSA)          // floats per A stage (9216 B)
#define BSTGH (NF * 32)           // halves per B stage (24576 B)
#define PSMEM (3 * (ASTGF * 4 + BSTGH * 2))   // 101376 B

__global__ __launch_bounds__(256, 2) void proj_kernel(const float* __restrict__ x)
{
    extern __shared__ char smraw[];
    float*  As = (float*)smraw;                        // 3 stages
    __half* Bs = (__half*)(smraw + 3 * ASTGF * 4);     // 3 stages, swizzled
    const uint32_t Bs_u = (uint32_t)__cvta_generic_to_shared(Bs);

    const int tid  = threadIdx.x;
    const int warp = tid >> 5, lane = tid & 31;
    const int wm = warp >> 2, wn = warp & 3;           // 2m x 4n
    const int lr = lane >> 2, lc = lane & 3;
    const int m0 = blockIdx.x * 64;

    // ldmatrix lane base: row within B tile, swizzle selector, k-half
    const int brow  = wn * 96 + (lane & 15);
    const int bsel  = (brow >> 1) & 3;
    const int bln16 = lane >> 4;

    auto load_tile = [&](int s, int j) {
        float*  Ad = As + s * ASTGF;
        __half* Bd = Bs + s * BSTGH;
        const int k0 = j * 32;
        #pragma unroll
        for (int i = 0; i < 2; i++) {                  // A: 512 x 16B
            int c = tid + i * 256, r = c >> 3, q = c & 7;
            cpa16(Ad + r * RSA + q * 4, x + (size_t)(m0 + r) * C_ + k0 + q * 4);
        }
        #pragma unroll
        for (int i = 0; i < 6; i++) {                  // B: 1536 x 16B, swizzled
            int c = tid + i * 256, r = c >> 2, cc = c & 3;
            cpa16(Bd + r * 32 + ((cc ^ ((r >> 1) & 3)) * 8),
                  g_wh + (size_t)r * C_ + k0 + cc * 8);
        }
        CP_COMMIT;
    };

    load_tile(0, 0);
    load_tile(1, 1);

    float acc[2][12][4] = {};

    for (int j = 0; j < NKT; j++) {
        if (j < NKT - 2) { CP_WAIT(1); } else { CP_WAIT(0); }
        __syncthreads();

        const float*   Aj  = As + (j % 3) * ASTGF;
        const uint32_t Bju = Bs_u + (uint32_t)((j % 3) * BSTGH) * 2;

        #pragma unroll
        for (int ks = 0; ks < 2; ks++) {
            const int kb = ks * 16;
            unsigned a[2][4];
            #pragma unroll
            for (int mi = 0; mi < 2; mi++) {
                const int row = wm * 32 + mi * 16 + lr;
                float2 f0 = *(const float2*)(Aj + row * RSA + kb + 2 * lc);
                float2 f1 = *(const float2*)(Aj + (row + 8) * RSA + kb + 2 * lc);
                float2 f2 = *(const float2*)(Aj + row * RSA + kb + 2 * lc + 8);
                float2 f3 = *(const float2*)(Aj + (row + 8) * RSA + kb + 2 * lc + 8);
                __half2 h0 = __floats2half2_rn(f0.x, f0.y);
                __half2 h1 = __floats2half2_rn(f1.x, f1.y);
                __half2 h2 = __floats2half2_rn(f2.x, f2.y);
                __half2 h3 = __floats2half2_rn(f3.x, f3.y);
                a[mi][0] = *reinterpret_cast<unsigned*>(&h0);
                a[mi][1] = *reinterpret_cast<unsigned*>(&h1);
                a[mi][2] = *reinterpret_cast<unsigned*>(&h2);
                a[mi][3] = *reinterpret_cast<unsigned*>(&h3);
            }
            const uint32_t chnk = (uint32_t)(((2 * ks + bln16) ^ bsel) * 16);
            #pragma unroll
            for (int pr = 0; pr < 6; pr++) {
                unsigned b0, b1, b2, b3;
                LDSM_X4(b0, b1, b2, b3,
                        Bju + (uint32_t)(brow * 64 + pr * 1024) + chnk);
                MMA_F16(acc[0][2 * pr],     a[0], b0, b2);
                MMA_F16(acc[0][2 * pr + 1], a[0], b1, b3);
                MMA_F16(acc[1][2 * pr],     a[1], b0, b2);
                MMA_F16(acc[1][2 * pr + 1], a[1], b1, b3);
            }
        }

        if (j + 2 < NKT) load_tile((j + 2) % 3, j + 2);
    }

    // epilogue: fp16 outputs split across K/Q/V
    __half* const outp[3] = { g_k, g_q, g_v };
    #pragma unroll
    for (int mi = 0; mi < 2; mi++) {
        const int row0 = m0 + wm * 32 + mi * 16 + lr;
        #pragma unroll
        for (int ni = 0; ni < 12; ni++) {
            const int gcol = wn * 96 + ni * 8;
            __half* o = outp[gcol >> 7];
            const int col = (gcol & 127) + 2 * lc;
            __half2 h1 = __floats2half2_rn(acc[mi][ni][0], acc[mi][ni][1]);
            __half2 h2 = __floats2half2_rn(acc[mi][ni][2], acc[mi][ni][3]);
            *(__half2*)(o + (size_t)row0 * HS_ + col)       = h1;
            *(__half2*)(o + (size_t)(row0 + 8) * HS_ + col) = h2;
        }
    }
}

// ----------------------------------------------------------------------------
// Attention (unchanged from R7): flash-style, fp16 mma, ldmatrix frags.
// ----------------------------------------------------------------------------
__global__ __launch_bounds__(256, 2) void attn_kernel(float* __restrict__ out)
{
    extern __shared__ char smr[];
    float*  sc    = (float*)smr;                   // [64][68]
    float*  f_row = sc + 64 * 68;                  // [64]
    float*  l_row = f_row + 64;                    // [64]
    __half* ph    = (__half*)(l_row + 64);         // [64][72]
    __half* kt    = ph + 64 * 72;                  // [64][136]
    __half* qv    = kt + 64 * 136;                 // [64][136]
    const uint32_t ph_u = (uint32_t)__cvta_generic_to_shared(ph);
    const uint32_t kt_u = (uint32_t)__cvta_generic_to_shared(kt);
    const uint32_t qv_u = (uint32_t)__cvta_generic_to_shared(qv);

    const int b  = blockIdx.y;
    const int bt = blockIdx.x;
    const int tid = threadIdx.x;
    const int warp = tid >> 5, lane = tid & 31;
    const int band = (warp & 3) * 16;
    const int hf = warp >> 2;
    const int lr = lane >> 2, lc = lane & 3;
    const int t0 = bt * 64;
    const float scale = rsqrtf((float)C_);

    const uint32_t aK = kt_u + (uint32_t)((band + (lane & 15)) * 136 + (lane >> 4) * 8) * 2;
    const uint32_t bQ = qv_u + (uint32_t)((hf * 32 + (lane & 7) + (lane >> 4) * 8) * 136
                                          + ((lane >> 3) & 1) * 8) * 2;
    const uint32_t aP = ph_u + (uint32_t)((band + (lane & 15)) * 72 + (lane >> 4) * 8) * 2;
    const uint32_t bV = qv_u + (uint32_t)(((lane & 7) + ((lane >> 3) & 1) * 8) * 136
                                          + hf * 64 + (lane >> 4) * 8) * 2;

    for (int i = tid; i < 1024; i += 256) {
        int r = i >> 4, c = i & 15;
        *(uint4*)(kt + r * 136 + c * 8) =
            *(const uint4*)(g_k + (size_t)(b * T_ + t0 + r) * HS_ + c * 8);
    }

    float m_r[8], l_r[8];
    float oacc[8][4] = {};
    #pragma unroll
    for (int i = 0; i < 8; i++) { m_r[i] = -INFINITY; l_r[i] = 0.f; }

    const int n_stiles = bt + 1;
    for (int st = 0; st < n_stiles; st++) {
        const int s0 = st * 64;

        for (int i = tid; i < 1024; i += 256) {
            int r = i >> 4, c = i & 15;
            *(uint4*)(qv + r * 136 + c * 8) =
                *(const uint4*)(g_q + (size_t)(b * T_ + s0 + r) * HS_ + c * 8);
        }
        __syncthreads();

        float sacc[4][4] = {};
        #pragma unroll
        for (int kk = 0; kk < 8; kk++) {
            unsigned a[4];
            LDSM_X4(a[0], a[1], a[2], a[3], aK + kk * 32);
            unsigned q0, q1, q2, q3, r0, r1, r2, r3;
            LDSM_X4(q0, q1, q2, q3, bQ + kk * 32);
            LDSM_X4(r0, r1, r2, r3, bQ + 16 * 136 * 2 + kk * 32);
            MMA_F16(sacc[0], a, q0, q1);
            MMA_F16(sacc[1], a, q2, q3);
            MMA_F16(sacc[2], a, r0, r1);
            MMA_F16(sacc[3], a, r2, r3);
        }
        const bool diag = (st == bt);
        #pragma unroll
        for (int nt = 0; nt < 4; nt++) {
            const int row = band + lr, col = hf * 32 + nt * 8 + 2 * lc;
            const int tg = t0 + row, sg = s0 + col;
            sc[row * 68 + col]           = (!diag || sg     <= tg)     ? sacc[nt][0] * scale : -INFINITY;
            sc[row * 68 + col + 1]       = (!diag || sg + 1 <= tg)     ? sacc[nt][1] * scale : -INFINITY;
            sc[(row + 8) * 68 + col]     = (!diag || sg     <= tg + 8) ? sacc[nt][2] * scale : -INFINITY;
            sc[(row + 8) * 68 + col + 1] = (!diag || sg + 1 <= tg + 8) ? sacc[nt][3] * scale : -INFINITY;
        }
        __syncthreads();

        for (int i = tid; i < 1024; i += 256) {
            int r = i >> 4, c = i & 15;
            *(uint4*)(qv + r * 136 + c * 8) =
                *(const uint4*)(g_v + (size_t)(b * T_ + s0 + r) * HS_ + c * 8);
        }

        #pragma unroll
        for (int i = 0; i < 8; i++) {
            const int row = warp * 8 + i;
            float* prow = sc + row * 68;
            float s1 = prow[lane], s2 = prow[lane + 32];
            float mt = fmaxf(s1, s2);
            #pragma unroll
            for (int o = 16; o; o >>= 1) mt = fmaxf(mt, __shfl_xor_sync(0xffffffffu, mt, o));
            float mn = fmaxf(m_r[i], mt);
            float f = __expf(m_r[i] - mn);
            __half e1h = __float2half_rn(__expf(s1 - mn));
            __half e2h = __float2half_rn(__expf(s2 - mn));
            ph[row * 72 + lane]      = e1h;
            ph[row * 72 + lane + 32] = e2h;
            float sum = __half2float(e1h) + __half2float(e2h);
            #pragma unroll
            for (int o = 16; o; o >>= 1) sum += __shfl_xor_sync(0xffffffffu, sum, o);
            l_r[i] = l_r[i] * f + sum;
            m_r[i] = mn;
            if (lane == 0) f_row[row] = f;
        }
        __syncthreads();

        {
            const float f1 = f_row[band + lr], f2 = f_row[band + lr + 8];
            #pragma unroll
            for (int nt = 0; nt < 8; nt++) {
                oacc[nt][0] *= f1; oacc[nt][1] *= f1;
                oacc[nt][2] *= f2; oacc[nt][3] *= f2;
            }
        }

        #pragma unroll
        for (int kk = 0; kk < 4; kk++) {
            unsigned p[4];
            LDSM_X4(p[0], p[1], p[2], p[3], aP + kk * 32);
            #pragma unroll
            for (int np = 0; np < 4; np++) {
                unsigned v0, v1, v2, v3;
                LDSM_X4_T(v0, v1, v2, v3,
                          bV + (uint32_t)(kk * 16 * 136 + np * 16) * 2);
                MMA_F16(oacc[np * 2],     p, v0, v1);
                MMA_F16(oacc[np * 2 + 1], p, v2, v3);
            }
        }
        __syncthreads();
    }

    if (lane == 0) {
        #pragma unroll
        for (int i = 0; i < 8; i++) l_row[warp * 8 + i] = l_r[i];
    }
    __syncthreads();

    {
        const float inv1 = 1.f / l_row[band + lr];
        const float inv2 = 1.f / l_row[band + lr + 8];
        const size_t r1 = (size_t)(b * T_ + t0 + band + lr) * HS_;
        const size_t r2 = (size_t)(b * T_ + t0 + band + lr + 8) * HS_;
        #pragma unroll
        for (int nt = 0; nt < 8; nt++) {
            const int col = hf * 64 + nt * 8 + 2 * lc;
            *(float2*)(out + r1 + col) = make_float2(oacc[nt][0] * inv1, oacc[nt][1] * inv1);
            *(float2*)(out + r2 + col) = make_float2(oacc[nt][2] * inv2, oacc[nt][3] * inv2);
        }
    }
}

// ----------------------------------------------------------------------------
extern "C" void kernel_launch(void* const* d_in, const int* in_sizes, int n_in,
                              void* d_out, int out_size)
{
    (void)in_sizes; (void)n_in; (void)out_size;
    const float* x  = (const float*)d_in[0];
    const float* Wk = (const float*)d_in[1];
    const float* Wq = (const float*)d_in[2];
    const float* Wv = (const float*)d_in[3];

    prep_wt<<<dim3(C_ / 32, HS_ / 32, 3), 256>>>(Wk, Wq, Wv);

    cudaFuncSetAttribute(proj_kernel, cudaFuncAttributeMaxDynamicSharedMemorySize, PSMEM);
    proj_kernel<<<M_ / 64, 256, PSMEM>>>(x);

    const int asmem = 64 * 68 * 4 + 128 * 4 + 64 * 72 * 2 + 2 * 64 * 136 * 2;  // 61952
    cudaFuncSetAttribute(attn_kernel, cudaFuncAttributeMaxDynamicSharedMemorySize, asmem);
    attn_kernel<<<dim3(4, 64), 256, asmem>>>((float*)d_out);
}